// round 10
// baseline (speedup 1.0000x reference)
#include <cuda_runtime.h>
#include <cuda_fp16.h>
#include <math.h>

#define BATCH 512
#define EPS 1e-5f

// ---------------- scratch (no allocations allowed) ----------------
__device__ __half g_act1[BATCH * 24 * 24 * 256];   // NHWC half
__device__ __half g_act2[BATCH * 12 * 12 * 128];   // NHWC half (pooled)
__device__ float  g_out3[BATCH * 64 * 36];         // NCHW fp32 (attention path)
__device__ __half g_out3h[BATCH * 64 * 36];        // NCHW half (fc1 input)
__device__ __half g_fc1[BATCH * 512];
__device__ __half g_fc2[BATCH * 256];
__device__ float  g_q[BATCH * 64];
__device__ __half g_wt2[9 * 256 * 128];            // [tap][ic2][oc][2] pair-interleaved
__device__ __half g_wt3[9 * 128 * 64];
__device__ __half g_fc1wh[512 * 2304];
__device__ __half g_fc2wh[256 * 512];
__device__ __half g_attwh[64 * 256];

__device__ __forceinline__ void cp_async16(void* dst, const void* src) {
    unsigned d = (unsigned)__cvta_generic_to_shared(dst);
    asm volatile("cp.async.ca.shared.global [%0], [%1], 16;" :: "r"(d), "l"(src) : "memory");
}
__device__ __forceinline__ void cp_commit() {
    asm volatile("cp.async.commit_group;" ::: "memory");
}
__device__ __forceinline__ void cp_wait0() {
    asm volatile("cp.async.wait_group 0;" ::: "memory");
}

// ---------------- merged weight conversion kernel ----------------
#define N_WT2 (9 * 256 * 128)
#define N_WT3 (9 * 128 * 64)
#define N_FC1 (512 * 2304)
#define N_FC2 (256 * 512)
#define N_ATT (64 * 256)
__global__ void convert_all_kernel(const float* __restrict__ c2w, const float* __restrict__ c3w,
                                   const float* __restrict__ fc1w, const float* __restrict__ fc2w,
                                   const float* __restrict__ attw,
                                   __half* __restrict__ wt2, __half* __restrict__ wt3,
                                   __half* __restrict__ fc1wh, __half* __restrict__ fc2wh,
                                   __half* __restrict__ attwh) {
    const int total = N_WT2 + N_WT3 + N_FC1 + N_FC2 + N_ATT;
    for (int idx = blockIdx.x * blockDim.x + threadIdx.x; idx < total;
         idx += gridDim.x * blockDim.x) {
        int i = idx;
        if (i < N_WT2) {
            int t = i / (256 * 128);
            int ic = (i / 128) % 256;
            int oc = i % 128;
            float v = c2w[((size_t)oc * 256 + ic) * 9 + t];
            wt2[(((size_t)t * 128 + (ic >> 1)) * 128 + oc) * 2 + (ic & 1)] = __float2half_rn(v);
            continue;
        }
        i -= N_WT2;
        if (i < N_WT3) {
            int t = i / (128 * 64);
            int ic = (i / 64) % 128;
            int oc = i % 64;
            float v = c3w[((size_t)oc * 128 + ic) * 9 + t];
            wt3[(((size_t)t * 64 + (ic >> 1)) * 64 + oc) * 2 + (ic & 1)] = __float2half_rn(v);
            continue;
        }
        i -= N_WT3;
        if (i < N_FC1) { fc1wh[i] = __float2half_rn(fc1w[i]); continue; }
        i -= N_FC1;
        if (i < N_FC2) { fc2wh[i] = __float2half_rn(fc2w[i]); continue; }
        i -= N_FC2;
        attwh[i] = __float2half_rn(attw[i]);
    }
}

// ---------------- block1 (tensor core): conv(1->256,48x48)+BN+ReLU+pool -> NHWC half -----------
#define B1_AP 200
#define B1_WP 136
#define B1_PP 144
__global__ void __launch_bounds__(256, 1)
block1_tc_kernel(const float* __restrict__ x, const float* __restrict__ w,
                 const float* __restrict__ cb, const float* __restrict__ gg,
                 const float* __restrict__ bb, const float* __restrict__ mm,
                 const float* __restrict__ vv, __half* __restrict__ out) {
    extern __shared__ unsigned smem_u[];
    unsigned* aw = smem_u;                       // [8][B1_AP]
    unsigned* ww = aw + 8 * B1_AP;               // [8][B1_WP]
    float* xt = (float*)(ww + 8 * B1_WP);        // [6][50]
    float* sInv = xt + 304;
    float* sBias = sInv + 128;
    __half* pout = (__half*)(sBias + 128);       // [192][B1_PP]

    int strip = blockIdx.x >> 1;
    int nhalf = blockIdx.x & 1;
    int b = blockIdx.y;
    int r0 = strip * 4;
    int oc0 = nhalf * 128;
    int tid = threadIdx.x;
    int warp = tid >> 5, lane = tid & 31;
    int g = lane >> 2, tig = lane & 3;
    int warpM = warp >> 1, warpN = warp & 1;

    const float* xb = x + (size_t)b * 48 * 48;
    for (int i = tid; i < 300; i += 256) {
        int r = i / 50, c = i % 50;
        int gr = r0 - 1 + r, gc = c - 1;
        float v = 0.f;
        if (gr >= 0 && gr < 48 && gc >= 0 && gc < 48) v = xb[gr * 48 + gc];
        xt[r * 50 + c] = v;
    }
    for (int i = tid; i < 8 * 128; i += 256) {
        int k2 = i >> 7, oc = i & 127;
        int t0 = 2 * k2, t1 = 2 * k2 + 1;
        float w0 = (t0 < 9) ? w[(size_t)(oc0 + oc) * 9 + t0] : 0.f;
        float w1 = (t1 < 9) ? w[(size_t)(oc0 + oc) * 9 + t1] : 0.f;
        __half2 h = __floats2half2_rn(w0, w1);
        ww[k2 * B1_WP + oc] = *(unsigned*)&h;
    }
    if (tid < 128) {
        int oc = oc0 + tid;
        float inv = gg[oc] * rsqrtf(vv[oc] + EPS);
        sInv[tid] = inv;
        sBias[tid] = (cb[oc] - mm[oc]) * inv + bb[oc];
    }
    __syncthreads();

    for (int i = tid; i < 8 * 192; i += 256) {
        int k2 = i / 192, m = i % 192;
        int mr = m / 48, mc = m % 48;
        int t0 = 2 * k2, t1 = t0 + 1;
        float v0 = 0.f, v1 = 0.f;
        if (t0 < 9) v0 = xt[(mr + t0 / 3) * 50 + mc + t0 % 3];
        if (t1 < 9) v1 = xt[(mr + t1 / 3) * 50 + mc + t1 % 3];
        __half2 h = __floats2half2_rn(v0, v1);
        aw[k2 * B1_AP + m] = *(unsigned*)&h;
    }
    __syncthreads();

    float acc[3][8][4];
#pragma unroll
    for (int mt = 0; mt < 3; mt++)
#pragma unroll
        for (int nt = 0; nt < 8; nt++)
#pragma unroll
            for (int i = 0; i < 4; i++) acc[mt][nt][i] = 0.f;

#pragma unroll
    for (int mt = 0; mt < 3; mt++) {
        int mbase = warpM * 48 + mt * 16 + g;
        unsigned a0 = aw[tig * B1_AP + mbase];
        unsigned a1 = aw[tig * B1_AP + mbase + 8];
        unsigned a2 = aw[(tig + 4) * B1_AP + mbase];
        unsigned a3 = aw[(tig + 4) * B1_AP + mbase + 8];
#pragma unroll
        for (int nt = 0; nt < 8; nt++) {
            int n = warpN * 64 + nt * 8 + g;
            unsigned b0 = ww[tig * B1_WP + n];
            unsigned b1 = ww[(tig + 4) * B1_WP + n];
            asm volatile(
                "mma.sync.aligned.m16n8k16.row.col.f32.f16.f16.f32 "
                "{%0,%1,%2,%3}, {%4,%5,%6,%7}, {%8,%9}, {%0,%1,%2,%3};"
                : "+f"(acc[mt][nt][0]), "+f"(acc[mt][nt][1]),
                  "+f"(acc[mt][nt][2]), "+f"(acc[mt][nt][3])
                : "r"(a0), "r"(a1), "r"(a2), "r"(a3), "r"(b0), "r"(b1));
        }
    }

#pragma unroll
    for (int mt = 0; mt < 3; mt++) {
        int m = warpM * 48 + mt * 16 + g;
#pragma unroll
        for (int nt = 0; nt < 8; nt++) {
            int oc = warpN * 64 + nt * 8 + tig * 2;
            float inv0 = sInv[oc], bi0 = sBias[oc];
            float inv1 = sInv[oc + 1], bi1 = sBias[oc + 1];
            __half2 v;
            v.x = __float2half_rn(fmaxf(fmaf(acc[mt][nt][0], inv0, bi0), 0.f));
            v.y = __float2half_rn(fmaxf(fmaf(acc[mt][nt][1], inv1, bi1), 0.f));
            *(__half2*)&pout[(size_t)m * B1_PP + oc] = v;
            v.x = __float2half_rn(fmaxf(fmaf(acc[mt][nt][2], inv0, bi0), 0.f));
            v.y = __float2half_rn(fmaxf(fmaf(acc[mt][nt][3], inv1, bi1), 0.f));
            *(__half2*)&pout[(size_t)(m + 8) * B1_PP + oc] = v;
        }
    }
    __syncthreads();

    for (int o = tid; o < 2 * 24 * 128; o += 256) {
        int oc = o & 127;
        int rest = o >> 7;
        int pc = rest % 24, pr = rest / 24;
        int m00 = (2 * pr) * 48 + 2 * pc;
        float a0 = __half2float(pout[(size_t)m00 * B1_PP + oc]);
        float a1 = __half2float(pout[(size_t)(m00 + 1) * B1_PP + oc]);
        float a2 = __half2float(pout[(size_t)(m00 + 48) * B1_PP + oc]);
        float a3 = __half2float(pout[(size_t)(m00 + 49) * B1_PP + oc]);
        float mx = fmaxf(fmaxf(a0, a1), fmaxf(a2, a3));
        int prow = strip * 2 + pr;
        out[(((size_t)b * 24 + prow) * 24 + pc) * 256 + oc0 + oc] = __float2half_rn(mx);
    }
}

// ---------------- fp16 tensor-core implicit-GEMM conv + BN + ReLU + fused 2x2 maxpool ----------
// MODE 0: pooled NHWC half output (conv2 -> act2). MODE 1: pooled NCHW float+half (conv3 -> out3).
template <int CIN, int COUT, int WIDTH, int SLAB, int RPW, int WM, int WN, int APITCH, int WPITCH,
          int OCC, int MODE>
__global__ void __launch_bounds__(WM * WN * 32, OCC)
conv_tc_kernel(const __half* __restrict__ act, const __half* __restrict__ wt,
               const float* __restrict__ cb, const float* __restrict__ gg,
               const float* __restrict__ bb, const float* __restrict__ mm,
               const float* __restrict__ vv,
               __half* __restrict__ out_h, float* __restrict__ out_f) {
    constexpr int ICB = 32;
    constexpr int KW = ICB / 2;
    constexpr int HC = WIDTH + 2;
    constexpr int NPOS = (SLAB + 2) * HC;
    constexpr int NT = WM * WN * 32;
    constexpr int NPW = COUT / WN;
    constexpr int NT2 = NPW / 8;
    constexpr int MT = (SLAB * WIDTH) / (WM * 16);
    constexpr int NCH = CIN / ICB;
    constexpr int ITERS = NCH * 9;
    constexpr int QW = KW * COUT / 4;
    constexpr int PFQ = (QW + NT - 1) / NT;
    constexpr int POOLW = WIDTH / 2;
    constexpr int SP = SLAB / 2;

    extern __shared__ float smem[];
    unsigned* atile = (unsigned*)smem;
    unsigned* wsm = (unsigned*)(smem + KW * APITCH);
    float* sInv = smem + KW * APITCH + 2 * KW * WPITCH;
    float* sBias = sInv + COUT;
    __half* stage = (__half*)smem;               // reused post-mainloop

    int b = blockIdx.y;
    int r0 = blockIdx.x * SLAB;
    int tid = threadIdx.x;
    int warp = tid >> 5, lane = tid & 31;
    int g = lane >> 2, tig = lane & 3;
    int warpM = warp / WN, warpN = warp % WN;

    if (tid < COUT) {
        float inv = gg[tid] * rsqrtf(vv[tid] + EPS);
        sInv[tid] = inv;
        sBias[tid] = (cb[tid] - mm[tid]) * inv + bb[tid];
    }

    const __half* actb = act + (size_t)b * WIDTH * WIDTH * CIN;

    float acc[MT][NT2][4];
#pragma unroll
    for (int mt = 0; mt < MT; mt++)
#pragma unroll
        for (int nt = 0; nt < NT2; nt++)
#pragma unroll
            for (int i = 0; i < 4; i++) acc[mt][nt][i] = 0.f;

    auto load_atile = [&](int ic0) {
        for (int i = tid; i < NPOS * (KW / 4); i += NT) {
            int pos = i >> 2, kq = i & 3;
            int tr = pos / HC, tc = pos % HC;
            int ir = r0 - 1 + tr, icl = tc - 1;
            uint4 v = make_uint4(0u, 0u, 0u, 0u);
            if (ir >= 0 && ir < WIDTH && icl >= 0 && icl < WIDTH)
                v = *(const uint4*)&actb[((size_t)ir * WIDTH + icl) * CIN + ic0 + kq * 8];
            int k2 = kq * 4;
            atile[(k2 + 0) * APITCH + pos] = v.x;
            atile[(k2 + 1) * APITCH + pos] = v.y;
            atile[(k2 + 2) * APITCH + pos] = v.z;
            atile[(k2 + 3) * APITCH + pos] = v.w;
        }
    };
    auto cpw = [&](int it, int buf) {
        const char* base = (const char*)((const unsigned*)wt
            + ((size_t)(it % 9) * (CIN / 2) + (it / 9) * KW) * COUT);
        unsigned* wb = wsm + buf * KW * WPITCH;
#pragma unroll
        for (int q = 0; q < PFQ; q++) {
            int idx = tid + q * NT;
            if (idx < QW) {
                int k2 = idx / (COUT / 4), nq = idx % (COUT / 4);
                cp_async16(&wb[k2 * WPITCH + nq * 4], base + (size_t)idx * 16);
            }
        }
        cp_commit();
    };

    cpw(0, 0);
    load_atile(0);
    cp_wait0();
    __syncthreads();

    for (int it = 0; it < ITERS; ++it) {
        int buf = it & 1;
        if (it + 1 < ITERS) cpw(it + 1, buf ^ 1);

        int tap = it % 9;
        int dy = tap / 3, dx = tap % 3;
        int pl[MT], ph[MT];
#pragma unroll
        for (int mt = 0; mt < MT; mt++) {
            int m = mt * 16 + g;
            pl[mt] = (warpM * RPW + m / WIDTH + dy) * HC + m % WIDTH + dx;
            m += 8;
            ph[mt] = (warpM * RPW + m / WIDTH + dy) * HC + m % WIDTH + dx;
        }
        const unsigned* wb = wsm + buf * KW * WPITCH;
#pragma unroll
        for (int ks = 0; ks < 2; ks++) {
            int k2c = ks * 8 + tig;
            unsigned af[MT][4];
#pragma unroll
            for (int mt = 0; mt < MT; mt++) {
                af[mt][0] = atile[k2c * APITCH + pl[mt]];
                af[mt][1] = atile[k2c * APITCH + ph[mt]];
                af[mt][2] = atile[(k2c + 4) * APITCH + pl[mt]];
                af[mt][3] = atile[(k2c + 4) * APITCH + ph[mt]];
            }
#pragma unroll
            for (int nt = 0; nt < NT2; nt++) {
                int n = warpN * NPW + nt * 8 + g;
                unsigned b0 = wb[k2c * WPITCH + n];
                unsigned b1 = wb[(k2c + 4) * WPITCH + n];
#pragma unroll
                for (int mt = 0; mt < MT; mt++) {
                    asm volatile(
                        "mma.sync.aligned.m16n8k16.row.col.f32.f16.f16.f32 "
                        "{%0,%1,%2,%3}, {%4,%5,%6,%7}, {%8,%9}, {%0,%1,%2,%3};"
                        : "+f"(acc[mt][nt][0]), "+f"(acc[mt][nt][1]),
                          "+f"(acc[mt][nt][2]), "+f"(acc[mt][nt][3])
                        : "r"(af[mt][0]), "r"(af[mt][1]), "r"(af[mt][2]), "r"(af[mt][3]),
                          "r"(b0), "r"(b1));
                }
            }
        }
        if (it + 1 < ITERS) {
            if ((it + 1) % 9 == 0) {
                __syncthreads();
                load_atile(((it + 1) / 9) * ICB);
            }
            cp_wait0();
        }
        __syncthreads();
    }

    // ---- fused epilogue: BN + ReLU -> stage smem, 2x2 maxpool -> global ----
    constexpr int SPITCH = NPW + 8;
    if (MODE == 0) {
        for (int p = 0; p < WN; p++) {
            if (warpN == p) {
#pragma unroll
                for (int mt = 0; mt < MT; mt++) {
                    int m = mt * 16 + g;
                    int pos = (warpM * RPW + m / WIDTH) * WIDTH + m % WIDTH;
                    int m2 = m + 8;
                    int pos2 = (warpM * RPW + m2 / WIDTH) * WIDTH + m2 % WIDTH;
#pragma unroll
                    for (int nt = 0; nt < NT2; nt++) {
                        int ocl = nt * 8 + tig * 2;
                        int oc = p * NPW + ocl;
                        float inv0 = sInv[oc], bi0 = sBias[oc];
                        float inv1 = sInv[oc + 1], bi1 = sBias[oc + 1];
                        __half2 v;
                        v.x = __float2half_rn(fmaxf(fmaf(acc[mt][nt][0], inv0, bi0), 0.f));
                        v.y = __float2half_rn(fmaxf(fmaf(acc[mt][nt][1], inv1, bi1), 0.f));
                        *(__half2*)&stage[(size_t)pos * SPITCH + ocl] = v;
                        v.x = __float2half_rn(fmaxf(fmaf(acc[mt][nt][2], inv0, bi0), 0.f));
                        v.y = __float2half_rn(fmaxf(fmaf(acc[mt][nt][3], inv1, bi1), 0.f));
                        *(__half2*)&stage[(size_t)pos2 * SPITCH + ocl] = v;
                    }
                }
            }
            __syncthreads();
            for (int o = tid; o < SP * POOLW * NPW; o += NT) {
                int ocl = o % NPW;
                int rest = o / NPW;
                int pc = rest % POOLW, pr = rest / POOLW;
                int m00 = (2 * pr) * WIDTH + 2 * pc;
                float a0 = __half2float(stage[(size_t)m00 * SPITCH + ocl]);
                float a1 = __half2float(stage[(size_t)(m00 + 1) * SPITCH + ocl]);
                float a2 = __half2float(stage[(size_t)(m00 + WIDTH) * SPITCH + ocl]);
                float a3 = __half2float(stage[(size_t)(m00 + WIDTH + 1) * SPITCH + ocl]);
                float mx = fmaxf(fmaxf(a0, a1), fmaxf(a2, a3));
                int prow = r0 / 2 + pr;
                out_h[(((size_t)b * POOLW + prow) * POOLW + pc) * COUT + p * NPW + ocl]
                    = __float2half_rn(mx);
            }
            __syncthreads();
        }
    } else {
        constexpr int SP2 = COUT + 8;
#pragma unroll
        for (int mt = 0; mt < MT; mt++) {
            int m = mt * 16 + g;
            int pos = (warpM * RPW + m / WIDTH) * WIDTH + m % WIDTH;
            int m2 = m + 8;
            int pos2 = (warpM * RPW + m2 / WIDTH) * WIDTH + m2 % WIDTH;
#pragma unroll
            for (int nt = 0; nt < NT2; nt++) {
                int oc = warpN * NPW + nt * 8 + tig * 2;
                float inv0 = sInv[oc], bi0 = sBias[oc];
                float inv1 = sInv[oc + 1], bi1 = sBias[oc + 1];
                __half2 v;
                v.x = __float2half_rn(fmaxf(fmaf(acc[mt][nt][0], inv0, bi0), 0.f));
                v.y = __float2half_rn(fmaxf(fmaf(acc[mt][nt][1], inv1, bi1), 0.f));
                *(__half2*)&stage[(size_t)pos * SP2 + oc] = v;
                v.x = __float2half_rn(fmaxf(fmaf(acc[mt][nt][2], inv0, bi0), 0.f));
                v.y = __float2half_rn(fmaxf(fmaf(acc[mt][nt][3], inv1, bi1), 0.f));
                *(__half2*)&stage[(size_t)pos2 * SP2 + oc] = v;
            }
        }
        __syncthreads();
        for (int o = tid; o < SP * POOLW * COUT; o += NT) {
            int oc = o % COUT;
            int rest = o / COUT;
            int pc = rest % POOLW, pr = rest / POOLW;
            int m00 = (2 * pr) * WIDTH + 2 * pc;
            float a0 = __half2float(stage[(size_t)m00 * SP2 + oc]);
            float a1 = __half2float(stage[(size_t)(m00 + 1) * SP2 + oc]);
            float a2 = __half2float(stage[(size_t)(m00 + WIDTH) * SP2 + oc]);
            float a3 = __half2float(stage[(size_t)(m00 + WIDTH + 1) * SP2 + oc]);
            float mx = fmaxf(fmaxf(a0, a1), fmaxf(a2, a3));
            int prow = r0 / 2 + pr;
            size_t oidx = (((size_t)b * COUT + oc) * POOLW + prow) * POOLW + pc;
            out_f[oidx] = mx;
            out_h[oidx] = __float2half_rn(mx);
        }
    }
}

// ---------------- fp16 tensor-core GEMM: C[M,N] = A[M,K] @ W[N,K]^T + bias ----------------
template <typename TOUT>
__global__ void __launch_bounds__(128) gemm_tc_kernel(const __half* __restrict__ A,
                                                      const __half* __restrict__ W,
                                                      const float* __restrict__ bias,
                                                      TOUT* __restrict__ C,
                                                      int M, int N, int K) {
    constexpr int AP = 65, WP = 33;
    __shared__ unsigned As[16 * AP];
    __shared__ unsigned Ws[16 * WP];

    int tid = threadIdx.x;
    int warp = tid >> 5, lane = tid & 31;
    int g = lane >> 2, tig = lane & 3;
    int warpM = warp >> 1, warpN = warp & 1;
    int row0 = blockIdx.y * 64;
    int col0 = blockIdx.x * 32;
    int K2 = K >> 1;
    const unsigned* A_u = (const unsigned*)A;
    const unsigned* W_u = (const unsigned*)W;

    float acc[2][2][4];
#pragma unroll
    for (int mt = 0; mt < 2; mt++)
#pragma unroll
        for (int nt = 0; nt < 2; nt++)
#pragma unroll
            for (int i = 0; i < 4; i++) acc[mt][nt][i] = 0.f;

    uint4 pa[2];
    uint4 pw;

    auto lA = [&](int k0) {
        int k2b = k0 >> 1;
#pragma unroll
        for (int q = 0; q < 2; q++) {
            int idx = tid + q * 128;
            int m = idx >> 2, kq = idx & 3;
            pa[q] = *(const uint4*)&A_u[(size_t)(row0 + m) * K2 + k2b + kq * 4];
        }
        {
            int n = tid >> 2, kq = tid & 3;
            pw = *(const uint4*)&W_u[(size_t)(col0 + n) * K2 + k2b + kq * 4];
        }
    };
    auto sA = [&]() {
#pragma unroll
        for (int q = 0; q < 2; q++) {
            int idx = tid + q * 128;
            int m = idx >> 2, k2 = (idx & 3) * 4;
            As[(k2 + 0) * AP + m] = pa[q].x;
            As[(k2 + 1) * AP + m] = pa[q].y;
            As[(k2 + 2) * AP + m] = pa[q].z;
            As[(k2 + 3) * AP + m] = pa[q].w;
        }
        {
            int n = tid >> 2, k2 = (tid & 3) * 4;
            Ws[(k2 + 0) * WP + n] = pw.x;
            Ws[(k2 + 1) * WP + n] = pw.y;
            Ws[(k2 + 2) * WP + n] = pw.z;
            Ws[(k2 + 3) * WP + n] = pw.w;
        }
    };

    lA(0);
    sA();
    __syncthreads();

    for (int k0 = 0; k0 < K; k0 += 32) {
        if (k0 + 32 < K) lA(k0 + 32);
#pragma unroll
        for (int ks = 0; ks < 2; ks++) {
            int k2c = ks * 8 + tig;
            unsigned af[2][4];
#pragma unroll
            for (int mt = 0; mt < 2; mt++) {
                int m = warpM * 32 + mt * 16 + g;
                af[mt][0] = As[k2c * AP + m];
                af[mt][1] = As[k2c * AP + m + 8];
                af[mt][2] = As[(k2c + 4) * AP + m];
                af[mt][3] = As[(k2c + 4) * AP + m + 8];
            }
#pragma unroll
            for (int nt = 0; nt < 2; nt++) {
                int n = warpN * 16 + nt * 8 + g;
                unsigned b0 = Ws[k2c * WP + n];
                unsigned b1 = Ws[(k2c + 4) * WP + n];
#pragma unroll
                for (int mt = 0; mt < 2; mt++) {
                    asm volatile(
                        "mma.sync.aligned.m16n8k16.row.col.f32.f16.f16.f32 "
                        "{%0,%1,%2,%3}, {%4,%5,%6,%7}, {%8,%9}, {%0,%1,%2,%3};"
                        : "+f"(acc[mt][nt][0]), "+f"(acc[mt][nt][1]),
                          "+f"(acc[mt][nt][2]), "+f"(acc[mt][nt][3])
                        : "r"(af[mt][0]), "r"(af[mt][1]), "r"(af[mt][2]), "r"(af[mt][3]),
                          "r"(b0), "r"(b1));
                }
            }
        }
        __syncthreads();
        if (k0 + 32 < K) {
            sA();
            __syncthreads();
        }
    }

#pragma unroll
    for (int mt = 0; mt < 2; mt++) {
        int r = row0 + warpM * 32 + mt * 16 + g;
#pragma unroll
        for (int nt = 0; nt < 2; nt++) {
            int c = col0 + warpN * 16 + nt * 8 + tig * 2;
            float b0 = bias[c], b1 = bias[c + 1];
            C[(size_t)r * N + c] = (TOUT)(acc[mt][nt][0] + b0);
            C[(size_t)r * N + c + 1] = (TOUT)(acc[mt][nt][1] + b1);
            C[(size_t)(r + 8) * N + c] = (TOUT)(acc[mt][nt][2] + b0);
            C[(size_t)(r + 8) * N + c + 1] = (TOUT)(acc[mt][nt][3] + b1);
        }
    }
}

// ---------------- attention epilogue ----------------
__global__ void attention_kernel(const float* __restrict__ out3, const float* __restrict__ q,
                                 const float* __restrict__ fc3_w, const float* __restrict__ fc3_b,
                                 float* __restrict__ out) {
    int b = blockIdx.x;
    __shared__ float s3[64 * 36];
    __shared__ float sq[64];
    __shared__ float sc[36];
    __shared__ float sg[64];
    int tid = threadIdx.x;
    for (int i = tid; i < 64 * 36; i += 64) s3[i] = out3[(size_t)b * 64 * 36 + i];
    sq[tid] = q[(size_t)b * 64 + tid];
    __syncthreads();
    if (tid < 36) {
        float s = 0.f;
#pragma unroll
        for (int c = 0; c < 64; c++) s = fmaf(s3[c * 36 + tid], sq[c], s);
        sc[tid] = s;
    }
    __syncthreads();
    if (tid == 0) {
        float mx = sc[0];
        for (int i = 1; i < 36; i++) mx = fmaxf(mx, sc[i]);
        float sum = 0.f;
        for (int i = 0; i < 36; i++) { float e = expf(sc[i] - mx); sc[i] = e; sum += e; }
        float invs = 1.f / sum;
        for (int i = 0; i < 36; i++) sc[i] *= invs;
    }
    __syncthreads();
    {
        float s = 0.f;
#pragma unroll
        for (int hw = 0; hw < 36; hw++) s = fmaf(s3[tid * 36 + hw], sc[hw], s);
        sg[tid] = s;
    }
    __syncthreads();
    if (tid < 7) {
        float s = fc3_b[tid];
#pragma unroll
        for (int c = 0; c < 64; c++) s = fmaf(sg[c], fc3_w[tid * 64 + c], s);
        out[(size_t)b * 7 + tid] = s;
    }
}

// ---------------- launch ----------------
extern "C" void kernel_launch(void* const* d_in, const int* in_sizes, int n_in,
                              void* d_out, int out_size) {
    const float* x    = (const float*)d_in[0];
    const float* c1w  = (const float*)d_in[1];
    const float* c1b  = (const float*)d_in[2];
    const float* bn1g = (const float*)d_in[3];
    const float* bn1b = (const float*)d_in[4];
    const float* bn1m = (const float*)d_in[5];
    const float* bn1v = (const float*)d_in[6];
    const float* c2w  = (const float*)d_in[7];
    const float* c2b  = (const float*)d_in[8];
    const float* bn2g = (const float*)d_in[9];
    const float* bn2b = (const float*)d_in[10];
    const float* bn2m = (const float*)d_in[11];
    const float* bn2v = (const float*)d_in[12];
    const float* c3w  = (const float*)d_in[13];
    const float* c3b  = (const float*)d_in[14];
    const float* bn3g = (const float*)d_in[15];
    const float* bn3b = (const float*)d_in[16];
    const float* bn3m = (const float*)d_in[17];
    const float* bn3v = (const float*)d_in[18];
    const float* fc1w = (const float*)d_in[19];
    const float* fc1b = (const float*)d_in[20];
    const float* fc2w = (const float*)d_in[21];
    const float* fc2b = (const float*)d_in[22];
    const float* attw = (const float*)d_in[23];
    const float* attb = (const float*)d_in[24];
    const float* fc3w = (const float*)d_in[25];
    const float* fc3b = (const float*)d_in[26];
    float* outp = (float*)d_out;

    __half *p_act1, *p_act2, *p_out3h, *p_fc1, *p_fc2;
    __half *p_wt2, *p_wt3, *p_fc1wh, *p_fc2wh, *p_attwh;
    float *p_out3, *p_q;
    cudaGetSymbolAddress((void**)&p_act1, g_act1);
    cudaGetSymbolAddress((void**)&p_act2, g_act2);
    cudaGetSymbolAddress((void**)&p_out3, g_out3);
    cudaGetSymbolAddress((void**)&p_out3h, g_out3h);
    cudaGetSymbolAddress((void**)&p_fc1, g_fc1);
    cudaGetSymbolAddress((void**)&p_fc2, g_fc2);
    cudaGetSymbolAddress((void**)&p_q, g_q);
    cudaGetSymbolAddress((void**)&p_wt2, g_wt2);
    cudaGetSymbolAddress((void**)&p_wt3, g_wt3);
    cudaGetSymbolAddress((void**)&p_fc1wh, g_fc1wh);
    cudaGetSymbolAddress((void**)&p_fc2wh, g_fc2wh);
    cudaGetSymbolAddress((void**)&p_attwh, g_attwh);

    // conv2: APITCH 264 (==8 mod 32, bank-conflict-free A), conv3: SLAB=4/WM=1/WN=4, APITCH 104
    const int SMEM2 = (16 * 264 + 2 * 16 * 136 + 2 * 128) * 4;  // ~34.5 KB
    const int SMEM3 = (16 * 104 + 2 * 16 * 72 + 2 * 64) * 4;    // 16 KB
    const int SMEMB1 = (8 * B1_AP + 8 * B1_WP + 304 + 256) * 4 + 192 * B1_PP * 2;  // ~68.3 KB
    cudaFuncSetAttribute((const void*)conv_tc_kernel<256, 128, 24, 8, 2, 4, 2, 264, 136, 2, 0>,
                         cudaFuncAttributeMaxDynamicSharedMemorySize, SMEM2);
    cudaFuncSetAttribute((const void*)conv_tc_kernel<128, 64, 12, 4, 4, 1, 4, 104, 72, 6, 1>,
                         cudaFuncAttributeMaxDynamicSharedMemorySize, SMEM3);
    cudaFuncSetAttribute((const void*)block1_tc_kernel,
                         cudaFuncAttributeMaxDynamicSharedMemorySize, SMEMB1);

    // merged weight conversions (one launch)
    convert_all_kernel<<<832, 256>>>(c2w, c3w, fc1w, fc2w, attw,
                                     p_wt2, p_wt3, p_fc1wh, p_fc2wh, p_attwh);

    // block1 (tensor core) -> NHWC act1 (half)
    block1_tc_kernel<<<dim3(24, BATCH), 256, SMEMB1>>>(x, c1w, c1b, bn1g, bn1b, bn1m, bn1v, p_act1);

    // conv2 + fused pool -> act2 (half NHWC pooled)
    conv_tc_kernel<256, 128, 24, 8, 2, 4, 2, 264, 136, 2, 0>
        <<<dim3(3, BATCH), 256, SMEM2>>>(p_act1, p_wt2, c2b, bn2g, bn2b, bn2m, bn2v,
                                         p_act2, nullptr);

    // conv3 + fused pool -> out3 (fp32 NCHW) + out3h (half NCHW)
    // SLAB=4, WM=1, WN=4: 128 threads, MT=1, grid (3, 512) = 1536 CTAs, OCC=6
    conv_tc_kernel<128, 64, 12, 4, 4, 1, 4, 104, 72, 6, 1>
        <<<dim3(3, BATCH), 128, SMEM3>>>(p_act2, p_wt3, c3b, bn3g, bn3b, bn3m, bn3v,
                                         p_out3h, p_out3);

    // FCs (fp16 tensor core)
    gemm_tc_kernel<__half><<<dim3(512 / 32, BATCH / 64), 128>>>(p_out3h, p_fc1wh, fc1b, p_fc1, BATCH, 512, 2304);
    gemm_tc_kernel<__half><<<dim3(256 / 32, BATCH / 64), 128>>>(p_fc1, p_fc2wh, fc2b, p_fc2, BATCH, 256, 512);
    gemm_tc_kernel<float><<<dim3(64 / 32, BATCH / 64), 128>>>(p_fc2, p_attwh, attb, p_q, BATCH, 64, 256);

    // attention + fc3
    attention_kernel<<<BATCH, 64>>>(p_out3, p_q, fc3w, fc3b, outp);
}

// round 11
// speedup vs baseline: 1.5091x; 1.5091x over previous
#include <cuda_runtime.h>
#include <cuda_fp16.h>
#include <math.h>

#define BATCH 512
#define EPS 1e-5f

// ---------------- scratch (no allocations allowed) ----------------
__device__ __half g_act1[BATCH * 24 * 24 * 256];   // NHWC half
__device__ __half g_act2[BATCH * 12 * 12 * 128];   // NHWC half (pooled)
__device__ float  g_out3[BATCH * 64 * 36];         // NCHW fp32 (attention path)
__device__ __half g_out3h[BATCH * 64 * 36];        // NCHW half (fc1 input)
__device__ __half g_fc1[BATCH * 512];
__device__ __half g_fc2[BATCH * 256];
__device__ float  g_q[BATCH * 64];
__device__ __half g_wt2[9 * 256 * 128];            // [tap][ic2][oc][2] pair-interleaved
__device__ __half g_wt3[9 * 128 * 64];
__device__ __half g_fc1wh[512 * 2304];
__device__ __half g_fc2wh[256 * 512];
__device__ __half g_attwh[64 * 256];

__device__ __forceinline__ void cp_async16(void* dst, const void* src) {
    unsigned d = (unsigned)__cvta_generic_to_shared(dst);
    asm volatile("cp.async.ca.shared.global [%0], [%1], 16;" :: "r"(d), "l"(src) : "memory");
}
__device__ __forceinline__ void cp_commit() {
    asm volatile("cp.async.commit_group;" ::: "memory");
}
__device__ __forceinline__ void cp_wait0() {
    asm volatile("cp.async.wait_group 0;" ::: "memory");
}

// ---------------- merged weight conversion kernel ----------------
#define N_WT2 (9 * 256 * 128)
#define N_WT3 (9 * 128 * 64)
#define N_FC1 (512 * 2304)
#define N_FC2 (256 * 512)
#define N_ATT (64 * 256)
__global__ void convert_all_kernel(const float* __restrict__ c2w, const float* __restrict__ c3w,
                                   const float* __restrict__ fc1w, const float* __restrict__ fc2w,
                                   const float* __restrict__ attw,
                                   __half* __restrict__ wt2, __half* __restrict__ wt3,
                                   __half* __restrict__ fc1wh, __half* __restrict__ fc2wh,
                                   __half* __restrict__ attwh) {
    const int total = N_WT2 + N_WT3 + N_FC1 + N_FC2 + N_ATT;
    for (int idx = blockIdx.x * blockDim.x + threadIdx.x; idx < total;
         idx += gridDim.x * blockDim.x) {
        int i = idx;
        if (i < N_WT2) {
            int t = i / (256 * 128);
            int ic = (i / 128) % 256;
            int oc = i % 128;
            float v = c2w[((size_t)oc * 256 + ic) * 9 + t];
            wt2[(((size_t)t * 128 + (ic >> 1)) * 128 + oc) * 2 + (ic & 1)] = __float2half_rn(v);
            continue;
        }
        i -= N_WT2;
        if (i < N_WT3) {
            int t = i / (128 * 64);
            int ic = (i / 64) % 128;
            int oc = i % 64;
            float v = c3w[((size_t)oc * 128 + ic) * 9 + t];
            wt3[(((size_t)t * 64 + (ic >> 1)) * 64 + oc) * 2 + (ic & 1)] = __float2half_rn(v);
            continue;
        }
        i -= N_WT3;
        if (i < N_FC1) { fc1wh[i] = __float2half_rn(fc1w[i]); continue; }
        i -= N_FC1;
        if (i < N_FC2) { fc2wh[i] = __float2half_rn(fc2w[i]); continue; }
        i -= N_FC2;
        attwh[i] = __float2half_rn(attw[i]);
    }
}

// ---------------- block1 (tensor core): conv(1->256,48x48)+BN+ReLU+pool -> NHWC half -----------
#define B1_AP 200
#define B1_WP 136
#define B1_PP 144
__global__ void __launch_bounds__(256, 1)
block1_tc_kernel(const float* __restrict__ x, const float* __restrict__ w,
                 const float* __restrict__ cb, const float* __restrict__ gg,
                 const float* __restrict__ bb, const float* __restrict__ mm,
                 const float* __restrict__ vv, __half* __restrict__ out) {
    extern __shared__ unsigned smem_u[];
    unsigned* aw = smem_u;                       // [8][B1_AP]
    unsigned* ww = aw + 8 * B1_AP;               // [8][B1_WP]
    float* xt = (float*)(ww + 8 * B1_WP);        // [6][50]
    float* sInv = xt + 304;
    float* sBias = sInv + 128;
    __half* pout = (__half*)(sBias + 128);       // [192][B1_PP]

    int strip = blockIdx.x >> 1;
    int nhalf = blockIdx.x & 1;
    int b = blockIdx.y;
    int r0 = strip * 4;
    int oc0 = nhalf * 128;
    int tid = threadIdx.x;
    int warp = tid >> 5, lane = tid & 31;
    int g = lane >> 2, tig = lane & 3;
    int warpM = warp >> 1, warpN = warp & 1;

    const float* xb = x + (size_t)b * 48 * 48;
    for (int i = tid; i < 300; i += 256) {
        int r = i / 50, c = i % 50;
        int gr = r0 - 1 + r, gc = c - 1;
        float v = 0.f;
        if (gr >= 0 && gr < 48 && gc >= 0 && gc < 48) v = xb[gr * 48 + gc];
        xt[r * 50 + c] = v;
    }
    for (int i = tid; i < 8 * 128; i += 256) {
        int k2 = i >> 7, oc = i & 127;
        int t0 = 2 * k2, t1 = 2 * k2 + 1;
        float w0 = (t0 < 9) ? w[(size_t)(oc0 + oc) * 9 + t0] : 0.f;
        float w1 = (t1 < 9) ? w[(size_t)(oc0 + oc) * 9 + t1] : 0.f;
        __half2 h = __floats2half2_rn(w0, w1);
        ww[k2 * B1_WP + oc] = *(unsigned*)&h;
    }
    if (tid < 128) {
        int oc = oc0 + tid;
        float inv = gg[oc] * rsqrtf(vv[oc] + EPS);
        sInv[tid] = inv;
        sBias[tid] = (cb[oc] - mm[oc]) * inv + bb[oc];
    }
    __syncthreads();

    for (int i = tid; i < 8 * 192; i += 256) {
        int k2 = i / 192, m = i % 192;
        int mr = m / 48, mc = m % 48;
        int t0 = 2 * k2, t1 = t0 + 1;
        float v0 = 0.f, v1 = 0.f;
        if (t0 < 9) v0 = xt[(mr + t0 / 3) * 50 + mc + t0 % 3];
        if (t1 < 9) v1 = xt[(mr + t1 / 3) * 50 + mc + t1 % 3];
        __half2 h = __floats2half2_rn(v0, v1);
        aw[k2 * B1_AP + m] = *(unsigned*)&h;
    }
    __syncthreads();

    float acc[3][8][4];
#pragma unroll
    for (int mt = 0; mt < 3; mt++)
#pragma unroll
        for (int nt = 0; nt < 8; nt++)
#pragma unroll
            for (int i = 0; i < 4; i++) acc[mt][nt][i] = 0.f;

#pragma unroll
    for (int mt = 0; mt < 3; mt++) {
        int mbase = warpM * 48 + mt * 16 + g;
        unsigned a0 = aw[tig * B1_AP + mbase];
        unsigned a1 = aw[tig * B1_AP + mbase + 8];
        unsigned a2 = aw[(tig + 4) * B1_AP + mbase];
        unsigned a3 = aw[(tig + 4) * B1_AP + mbase + 8];
#pragma unroll
        for (int nt = 0; nt < 8; nt++) {
            int n = warpN * 64 + nt * 8 + g;
            unsigned b0 = ww[tig * B1_WP + n];
            unsigned b1 = ww[(tig + 4) * B1_WP + n];
            asm volatile(
                "mma.sync.aligned.m16n8k16.row.col.f32.f16.f16.f32 "
                "{%0,%1,%2,%3}, {%4,%5,%6,%7}, {%8,%9}, {%0,%1,%2,%3};"
                : "+f"(acc[mt][nt][0]), "+f"(acc[mt][nt][1]),
                  "+f"(acc[mt][nt][2]), "+f"(acc[mt][nt][3])
                : "r"(a0), "r"(a1), "r"(a2), "r"(a3), "r"(b0), "r"(b1));
        }
    }

#pragma unroll
    for (int mt = 0; mt < 3; mt++) {
        int m = warpM * 48 + mt * 16 + g;
#pragma unroll
        for (int nt = 0; nt < 8; nt++) {
            int oc = warpN * 64 + nt * 8 + tig * 2;
            float inv0 = sInv[oc], bi0 = sBias[oc];
            float inv1 = sInv[oc + 1], bi1 = sBias[oc + 1];
            __half2 v;
            v.x = __float2half_rn(fmaxf(fmaf(acc[mt][nt][0], inv0, bi0), 0.f));
            v.y = __float2half_rn(fmaxf(fmaf(acc[mt][nt][1], inv1, bi1), 0.f));
            *(__half2*)&pout[(size_t)m * B1_PP + oc] = v;
            v.x = __float2half_rn(fmaxf(fmaf(acc[mt][nt][2], inv0, bi0), 0.f));
            v.y = __float2half_rn(fmaxf(fmaf(acc[mt][nt][3], inv1, bi1), 0.f));
            *(__half2*)&pout[(size_t)(m + 8) * B1_PP + oc] = v;
        }
    }
    __syncthreads();

    for (int o = tid; o < 2 * 24 * 128; o += 256) {
        int oc = o & 127;
        int rest = o >> 7;
        int pc = rest % 24, pr = rest / 24;
        int m00 = (2 * pr) * 48 + 2 * pc;
        float a0 = __half2float(pout[(size_t)m00 * B1_PP + oc]);
        float a1 = __half2float(pout[(size_t)(m00 + 1) * B1_PP + oc]);
        float a2 = __half2float(pout[(size_t)(m00 + 48) * B1_PP + oc]);
        float a3 = __half2float(pout[(size_t)(m00 + 49) * B1_PP + oc]);
        float mx = fmaxf(fmaxf(a0, a1), fmaxf(a2, a3));
        int prow = strip * 2 + pr;
        out[(((size_t)b * 24 + prow) * 24 + pc) * 256 + oc0 + oc] = __float2half_rn(mx);
    }
}

// ---------------- fp16 tensor-core implicit-GEMM conv + BN + ReLU + fused 2x2 maxpool ----------
// ICB channels per chunk (64 -> half the barriers of 32). R9-proven tilings only.
template <int CIN, int COUT, int WIDTH, int SLAB, int RPW, int WM, int WN, int APITCH, int WPITCH,
          int OCC, int MODE, int ICB>
__global__ void __launch_bounds__(WM * WN * 32, OCC)
conv_tc_kernel(const __half* __restrict__ act, const __half* __restrict__ wt,
               const float* __restrict__ cb, const float* __restrict__ gg,
               const float* __restrict__ bb, const float* __restrict__ mm,
               const float* __restrict__ vv,
               __half* __restrict__ out_h, float* __restrict__ out_f) {
    constexpr int KW = ICB / 2;                 // half2 words per chunk
    constexpr int KWQ = KW / 4;                 // uint4 groups per position
    constexpr int NKS = KW / 8;                 // k16 steps per tap
    constexpr int HC = WIDTH + 2;
    constexpr int NPOS = (SLAB + 2) * HC;
    constexpr int NT = WM * WN * 32;
    constexpr int NPW = COUT / WN;
    constexpr int NT2 = NPW / 8;
    constexpr int MT = (SLAB * WIDTH) / (WM * 16);
    constexpr int NCH = CIN / ICB;
    constexpr int ITERS = NCH * 9;
    constexpr int QW = KW * COUT / 4;
    constexpr int PFQ = (QW + NT - 1) / NT;
    constexpr int POOLW = WIDTH / 2;
    constexpr int SP = SLAB / 2;

    extern __shared__ float smem[];
    unsigned* atile = (unsigned*)smem;          // [KW][APITCH]
    unsigned* wsm = (unsigned*)(smem + KW * APITCH);  // [2][KW][WPITCH]
    float* sInv = smem + KW * APITCH + 2 * KW * WPITCH;
    float* sBias = sInv + COUT;
    __half* stage = (__half*)smem;              // reused post-mainloop

    int b = blockIdx.y;
    int r0 = blockIdx.x * SLAB;
    int tid = threadIdx.x;
    int warp = tid >> 5, lane = tid & 31;
    int g = lane >> 2, tig = lane & 3;
    int warpM = warp / WN, warpN = warp % WN;

    if (tid < COUT) {
        float inv = gg[tid] * rsqrtf(vv[tid] + EPS);
        sInv[tid] = inv;
        sBias[tid] = (cb[tid] - mm[tid]) * inv + bb[tid];
    }

    const __half* actb = act + (size_t)b * WIDTH * WIDTH * CIN;

    float acc[MT][NT2][4];
#pragma unroll
    for (int mt = 0; mt < MT; mt++)
#pragma unroll
        for (int nt = 0; nt < NT2; nt++)
#pragma unroll
            for (int i = 0; i < 4; i++) acc[mt][nt][i] = 0.f;

    auto load_atile = [&](int ic0) {
        for (int i = tid; i < NPOS * KWQ; i += NT) {
            int pos = i / KWQ, kq = i % KWQ;
            int tr = pos / HC, tc = pos % HC;
            int ir = r0 - 1 + tr, icl = tc - 1;
            uint4 v = make_uint4(0u, 0u, 0u, 0u);
            if (ir >= 0 && ir < WIDTH && icl >= 0 && icl < WIDTH)
                v = *(const uint4*)&actb[((size_t)ir * WIDTH + icl) * CIN + ic0 + kq * 8];
            int k2 = kq * 4;
            atile[(k2 + 0) * APITCH + pos] = v.x;
            atile[(k2 + 1) * APITCH + pos] = v.y;
            atile[(k2 + 2) * APITCH + pos] = v.z;
            atile[(k2 + 3) * APITCH + pos] = v.w;
        }
    };
    auto cpw = [&](int it, int buf) {
        const char* base = (const char*)((const unsigned*)wt
            + ((size_t)(it % 9) * (CIN / 2) + (it / 9) * KW) * COUT);
        unsigned* wb = wsm + buf * KW * WPITCH;
#pragma unroll
        for (int q = 0; q < PFQ; q++) {
            int idx = tid + q * NT;
            if (idx < QW) {
                int k2 = idx / (COUT / 4), nq = idx % (COUT / 4);
                cp_async16(&wb[k2 * WPITCH + nq * 4], base + (size_t)idx * 16);
            }
        }
        cp_commit();
    };

    cpw(0, 0);
    load_atile(0);
    cp_wait0();
    __syncthreads();

    for (int it = 0; it < ITERS; ++it) {
        int buf = it & 1;
        if (it + 1 < ITERS) cpw(it + 1, buf ^ 1);

        int tap = it % 9;
        int dy = tap / 3, dx = tap % 3;
        int pl[MT], ph[MT];
#pragma unroll
        for (int mt = 0; mt < MT; mt++) {
            int m = mt * 16 + g;
            pl[mt] = (warpM * RPW + m / WIDTH + dy) * HC + m % WIDTH + dx;
            m += 8;
            ph[mt] = (warpM * RPW + m / WIDTH + dy) * HC + m % WIDTH + dx;
        }
        const unsigned* wb = wsm + buf * KW * WPITCH;
#pragma unroll
        for (int ks = 0; ks < NKS; ks++) {
            int k2c = ks * 8 + tig;
            unsigned af[MT][4];
#pragma unroll
            for (int mt = 0; mt < MT; mt++) {
                af[mt][0] = atile[k2c * APITCH + pl[mt]];
                af[mt][1] = atile[k2c * APITCH + ph[mt]];
                af[mt][2] = atile[(k2c + 4) * APITCH + pl[mt]];
                af[mt][3] = atile[(k2c + 4) * APITCH + ph[mt]];
            }
#pragma unroll
            for (int nt = 0; nt < NT2; nt++) {
                int n = warpN * NPW + nt * 8 + g;
                unsigned b0 = wb[k2c * WPITCH + n];
                unsigned b1 = wb[(k2c + 4) * WPITCH + n];
#pragma unroll
                for (int mt = 0; mt < MT; mt++) {
                    asm volatile(
                        "mma.sync.aligned.m16n8k16.row.col.f32.f16.f16.f32 "
                        "{%0,%1,%2,%3}, {%4,%5,%6,%7}, {%8,%9}, {%0,%1,%2,%3};"
                        : "+f"(acc[mt][nt][0]), "+f"(acc[mt][nt][1]),
                          "+f"(acc[mt][nt][2]), "+f"(acc[mt][nt][3])
                        : "r"(af[mt][0]), "r"(af[mt][1]), "r"(af[mt][2]), "r"(af[mt][3]),
                          "r"(b0), "r"(b1));
                }
            }
        }
        if (it + 1 < ITERS) {
            if ((it + 1) % 9 == 0) {
                __syncthreads();
                load_atile(((it + 1) / 9) * ICB);
            }
            cp_wait0();
        }
        __syncthreads();
    }

    // ---- fused epilogue: BN + ReLU -> stage smem, 2x2 maxpool -> global ----
    constexpr int SPITCH = NPW + 8;
    if (MODE == 0) {
        for (int p = 0; p < WN; p++) {
            if (warpN == p) {
#pragma unroll
                for (int mt = 0; mt < MT; mt++) {
                    int m = mt * 16 + g;
                    int pos = (warpM * RPW + m / WIDTH) * WIDTH + m % WIDTH;
                    int m2 = m + 8;
                    int pos2 = (warpM * RPW + m2 / WIDTH) * WIDTH + m2 % WIDTH;
#pragma unroll
                    for (int nt = 0; nt < NT2; nt++) {
                        int ocl = nt * 8 + tig * 2;
                        int oc = p * NPW + ocl;
                        float inv0 = sInv[oc], bi0 = sBias[oc];
                        float inv1 = sInv[oc + 1], bi1 = sBias[oc + 1];
                        __half2 v;
                        v.x = __float2half_rn(fmaxf(fmaf(acc[mt][nt][0], inv0, bi0), 0.f));
                        v.y = __float2half_rn(fmaxf(fmaf(acc[mt][nt][1], inv1, bi1), 0.f));
                        *(__half2*)&stage[(size_t)pos * SPITCH + ocl] = v;
                        v.x = __float2half_rn(fmaxf(fmaf(acc[mt][nt][2], inv0, bi0), 0.f));
                        v.y = __float2half_rn(fmaxf(fmaf(acc[mt][nt][3], inv1, bi1), 0.f));
                        *(__half2*)&stage[(size_t)pos2 * SPITCH + ocl] = v;
                    }
                }
            }
            __syncthreads();
            for (int o = tid; o < SP * POOLW * NPW; o += NT) {
                int ocl = o % NPW;
                int rest = o / NPW;
                int pc = rest % POOLW, pr = rest / POOLW;
                int m00 = (2 * pr) * WIDTH + 2 * pc;
                float a0 = __half2float(stage[(size_t)m00 * SPITCH + ocl]);
                float a1 = __half2float(stage[(size_t)(m00 + 1) * SPITCH + ocl]);
                float a2 = __half2float(stage[(size_t)(m00 + WIDTH) * SPITCH + ocl]);
                float a3 = __half2float(stage[(size_t)(m00 + WIDTH + 1) * SPITCH + ocl]);
                float mx = fmaxf(fmaxf(a0, a1), fmaxf(a2, a3));
                int prow = r0 / 2 + pr;
                out_h[(((size_t)b * POOLW + prow) * POOLW + pc) * COUT + p * NPW + ocl]
                    = __float2half_rn(mx);
            }
            __syncthreads();
        }
    } else {
        constexpr int SP2 = COUT + 8;
#pragma unroll
        for (int mt = 0; mt < MT; mt++) {
            int m = mt * 16 + g;
            int pos = (warpM * RPW + m / WIDTH) * WIDTH + m % WIDTH;
            int m2 = m + 8;
            int pos2 = (warpM * RPW + m2 / WIDTH) * WIDTH + m2 % WIDTH;
#pragma unroll
            for (int nt = 0; nt < NT2; nt++) {
                int oc = warpN * NPW + nt * 8 + tig * 2;
                float inv0 = sInv[oc], bi0 = sBias[oc];
                float inv1 = sInv[oc + 1], bi1 = sBias[oc + 1];
                __half2 v;
                v.x = __float2half_rn(fmaxf(fmaf(acc[mt][nt][0], inv0, bi0), 0.f));
                v.y = __float2half_rn(fmaxf(fmaf(acc[mt][nt][1], inv1, bi1), 0.f));
                *(__half2*)&stage[(size_t)pos * SP2 + oc] = v;
                v.x = __float2half_rn(fmaxf(fmaf(acc[mt][nt][2], inv0, bi0), 0.f));
                v.y = __float2half_rn(fmaxf(fmaf(acc[mt][nt][3], inv1, bi1), 0.f));
                *(__half2*)&stage[(size_t)pos2 * SP2 + oc] = v;
            }
        }
        __syncthreads();
        for (int o = tid; o < SP * POOLW * COUT; o += NT) {
            int oc = o % COUT;
            int rest = o / COUT;
            int pc = rest % POOLW, pr = rest / POOLW;
            int m00 = (2 * pr) * WIDTH + 2 * pc;
            float a0 = __half2float(stage[(size_t)m00 * SP2 + oc]);
            float a1 = __half2float(stage[(size_t)(m00 + 1) * SP2 + oc]);
            float a2 = __half2float(stage[(size_t)(m00 + WIDTH) * SP2 + oc]);
            float a3 = __half2float(stage[(size_t)(m00 + WIDTH + 1) * SP2 + oc]);
            float mx = fmaxf(fmaxf(a0, a1), fmaxf(a2, a3));
            int prow = r0 / 2 + pr;
            size_t oidx = (((size_t)b * COUT + oc) * POOLW + prow) * POOLW + pc;
            out_f[oidx] = mx;
            out_h[oidx] = __float2half_rn(mx);
        }
    }
}

// ---------------- fp16 tensor-core GEMM: C[M,N] = A[M,K] @ W[N,K]^T + bias ----------------
template <typename TOUT>
__global__ void __launch_bounds__(128) gemm_tc_kernel(const __half* __restrict__ A,
                                                      const __half* __restrict__ W,
                                                      const float* __restrict__ bias,
                                                      TOUT* __restrict__ C,
                                                      int M, int N, int K) {
    constexpr int AP = 65, WP = 33;
    __shared__ unsigned As[16 * AP];
    __shared__ unsigned Ws[16 * WP];

    int tid = threadIdx.x;
    int warp = tid >> 5, lane = tid & 31;
    int g = lane >> 2, tig = lane & 3;
    int warpM = warp >> 1, warpN = warp & 1;
    int row0 = blockIdx.y * 64;
    int col0 = blockIdx.x * 32;
    int K2 = K >> 1;
    const unsigned* A_u = (const unsigned*)A;
    const unsigned* W_u = (const unsigned*)W;

    float acc[2][2][4];
#pragma unroll
    for (int mt = 0; mt < 2; mt++)
#pragma unroll
        for (int nt = 0; nt < 2; nt++)
#pragma unroll
            for (int i = 0; i < 4; i++) acc[mt][nt][i] = 0.f;

    uint4 pa[2];
    uint4 pw;

    auto lA = [&](int k0) {
        int k2b = k0 >> 1;
#pragma unroll
        for (int q = 0; q < 2; q++) {
            int idx = tid + q * 128;
            int m = idx >> 2, kq = idx & 3;
            pa[q] = *(const uint4*)&A_u[(size_t)(row0 + m) * K2 + k2b + kq * 4];
        }
        {
            int n = tid >> 2, kq = tid & 3;
            pw = *(const uint4*)&W_u[(size_t)(col0 + n) * K2 + k2b + kq * 4];
        }
    };
    auto sA = [&]() {
#pragma unroll
        for (int q = 0; q < 2; q++) {
            int idx = tid + q * 128;
            int m = idx >> 2, k2 = (idx & 3) * 4;
            As[(k2 + 0) * AP + m] = pa[q].x;
            As[(k2 + 1) * AP + m] = pa[q].y;
            As[(k2 + 2) * AP + m] = pa[q].z;
            As[(k2 + 3) * AP + m] = pa[q].w;
        }
        {
            int n = tid >> 2, k2 = (tid & 3) * 4;
            Ws[(k2 + 0) * WP + n] = pw.x;
            Ws[(k2 + 1) * WP + n] = pw.y;
            Ws[(k2 + 2) * WP + n] = pw.z;
            Ws[(k2 + 3) * WP + n] = pw.w;
        }
    };

    lA(0);
    sA();
    __syncthreads();

    for (int k0 = 0; k0 < K; k0 += 32) {
        if (k0 + 32 < K) lA(k0 + 32);
#pragma unroll
        for (int ks = 0; ks < 2; ks++) {
            int k2c = ks * 8 + tig;
            unsigned af[2][4];
#pragma unroll
            for (int mt = 0; mt < 2; mt++) {
                int m = warpM * 32 + mt * 16 + g;
                af[mt][0] = As[k2c * AP + m];
                af[mt][1] = As[k2c * AP + m + 8];
                af[mt][2] = As[(k2c + 4) * AP + m];
                af[mt][3] = As[(k2c + 4) * AP + m + 8];
            }
#pragma unroll
            for (int nt = 0; nt < 2; nt++) {
                int n = warpN * 16 + nt * 8 + g;
                unsigned b0 = Ws[k2c * WP + n];
                unsigned b1 = Ws[(k2c + 4) * WP + n];
#pragma unroll
                for (int mt = 0; mt < 2; mt++) {
                    asm volatile(
                        "mma.sync.aligned.m16n8k16.row.col.f32.f16.f16.f32 "
                        "{%0,%1,%2,%3}, {%4,%5,%6,%7}, {%8,%9}, {%0,%1,%2,%3};"
                        : "+f"(acc[mt][nt][0]), "+f"(acc[mt][nt][1]),
                          "+f"(acc[mt][nt][2]), "+f"(acc[mt][nt][3])
                        : "r"(af[mt][0]), "r"(af[mt][1]), "r"(af[mt][2]), "r"(af[mt][3]),
                          "r"(b0), "r"(b1));
                }
            }
        }
        __syncthreads();
        if (k0 + 32 < K) {
            sA();
            __syncthreads();
        }
    }

#pragma unroll
    for (int mt = 0; mt < 2; mt++) {
        int r = row0 + warpM * 32 + mt * 16 + g;
#pragma unroll
        for (int nt = 0; nt < 2; nt++) {
            int c = col0 + warpN * 16 + nt * 8 + tig * 2;
            float b0 = bias[c], b1 = bias[c + 1];
            C[(size_t)r * N + c] = (TOUT)(acc[mt][nt][0] + b0);
            C[(size_t)r * N + c + 1] = (TOUT)(acc[mt][nt][1] + b1);
            C[(size_t)(r + 8) * N + c] = (TOUT)(acc[mt][nt][2] + b0);
            C[(size_t)(r + 8) * N + c + 1] = (TOUT)(acc[mt][nt][3] + b1);
        }
    }
}

// ---------------- attention epilogue ----------------
__global__ void attention_kernel(const float* __restrict__ out3, const float* __restrict__ q,
                                 const float* __restrict__ fc3_w, const float* __restrict__ fc3_b,
                                 float* __restrict__ out) {
    int b = blockIdx.x;
    __shared__ float s3[64 * 36];
    __shared__ float sq[64];
    __shared__ float sc[36];
    __shared__ float sg[64];
    int tid = threadIdx.x;
    for (int i = tid; i < 64 * 36; i += 64) s3[i] = out3[(size_t)b * 64 * 36 + i];
    sq[tid] = q[(size_t)b * 64 + tid];
    __syncthreads();
    if (tid < 36) {
        float s = 0.f;
#pragma unroll
        for (int c = 0; c < 64; c++) s = fmaf(s3[c * 36 + tid], sq[c], s);
        sc[tid] = s;
    }
    __syncthreads();
    if (tid == 0) {
        float mx = sc[0];
        for (int i = 1; i < 36; i++) mx = fmaxf(mx, sc[i]);
        float sum = 0.f;
        for (int i = 0; i < 36; i++) { float e = expf(sc[i] - mx); sc[i] = e; sum += e; }
        float invs = 1.f / sum;
        for (int i = 0; i < 36; i++) sc[i] *= invs;
    }
    __syncthreads();
    {
        float s = 0.f;
#pragma unroll
        for (int hw = 0; hw < 36; hw++) s = fmaf(s3[tid * 36 + hw], sc[hw], s);
        sg[tid] = s;
    }
    __syncthreads();
    if (tid < 7) {
        float s = fc3_b[tid];
#pragma unroll
        for (int c = 0; c < 64; c++) s = fmaf(sg[c], fc3_w[tid * 64 + c], s);
        out[(size_t)b * 7 + tid] = s;
    }
}

// ---------------- launch ----------------
extern "C" void kernel_launch(void* const* d_in, const int* in_sizes, int n_in,
                              void* d_out, int out_size) {
    const float* x    = (const float*)d_in[0];
    const float* c1w  = (const float*)d_in[1];
    const float* c1b  = (const float*)d_in[2];
    const float* bn1g = (const float*)d_in[3];
    const float* bn1b = (const float*)d_in[4];
    const float* bn1m = (const float*)d_in[5];
    const float* bn1v = (const float*)d_in[6];
    const float* c2w  = (const float*)d_in[7];
    const float* c2b  = (const float*)d_in[8];
    const float* bn2g = (const float*)d_in[9];
    const float* bn2b = (const float*)d_in[10];
    const float* bn2m = (const float*)d_in[11];
    const float* bn2v = (const float*)d_in[12];
    const float* c3w  = (const float*)d_in[13];
    const float* c3b  = (const float*)d_in[14];
    const float* bn3g = (const float*)d_in[15];
    const float* bn3b = (const float*)d_in[16];
    const float* bn3m = (const float*)d_in[17];
    const float* bn3v = (const float*)d_in[18];
    const float* fc1w = (const float*)d_in[19];
    const float* fc1b = (const float*)d_in[20];
    const float* fc2w = (const float*)d_in[21];
    const float* fc2b = (const float*)d_in[22];
    const float* attw = (const float*)d_in[23];
    const float* attb = (const float*)d_in[24];
    const float* fc3w = (const float*)d_in[25];
    const float* fc3b = (const float*)d_in[26];
    float* outp = (float*)d_out;

    __half *p_act1, *p_act2, *p_out3h, *p_fc1, *p_fc2;
    __half *p_wt2, *p_wt3, *p_fc1wh, *p_fc2wh, *p_attwh;
    float *p_out3, *p_q;
    cudaGetSymbolAddress((void**)&p_act1, g_act1);
    cudaGetSymbolAddress((void**)&p_act2, g_act2);
    cudaGetSymbolAddress((void**)&p_out3, g_out3);
    cudaGetSymbolAddress((void**)&p_out3h, g_out3h);
    cudaGetSymbolAddress((void**)&p_fc1, g_fc1);
    cudaGetSymbolAddress((void**)&p_fc2, g_fc2);
    cudaGetSymbolAddress((void**)&p_q, g_q);
    cudaGetSymbolAddress((void**)&p_wt2, g_wt2);
    cudaGetSymbolAddress((void**)&p_wt3, g_wt3);
    cudaGetSymbolAddress((void**)&p_fc1wh, g_fc1wh);
    cudaGetSymbolAddress((void**)&p_fc2wh, g_fc2wh);
    cudaGetSymbolAddress((void**)&p_attwh, g_attwh);

    // R9 tilings, ICB=64: conv2 APITCH 261, conv3 SLAB=12/WM=3/WN=2 APITCH 197
    const int SMEM2 = (32 * 261 + 2 * 32 * 136 + 2 * 128) * 4;  // ~68.8 KB
    const int SMEM3 = (32 * 197 + 2 * 32 * 72 + 2 * 64) * 4;    // ~44.1 KB
    const int SMEMB1 = (8 * B1_AP + 8 * B1_WP + 304 + 256) * 4 + 192 * B1_PP * 2;  // ~68.3 KB
    cudaFuncSetAttribute((const void*)conv_tc_kernel<256, 128, 24, 8, 2, 4, 2, 261, 136, 2, 0, 64>,
                         cudaFuncAttributeMaxDynamicSharedMemorySize, SMEM2);
    cudaFuncSetAttribute((const void*)conv_tc_kernel<128, 64, 12, 12, 4, 3, 2, 197, 72, 3, 1, 64>,
                         cudaFuncAttributeMaxDynamicSharedMemorySize, SMEM3);
    cudaFuncSetAttribute((const void*)block1_tc_kernel,
                         cudaFuncAttributeMaxDynamicSharedMemorySize, SMEMB1);

    // merged weight conversions (one launch)
    convert_all_kernel<<<832, 256>>>(c2w, c3w, fc1w, fc2w, attw,
                                     p_wt2, p_wt3, p_fc1wh, p_fc2wh, p_attwh);

    // block1 (tensor core) -> NHWC act1 (half)
    block1_tc_kernel<<<dim3(24, BATCH), 256, SMEMB1>>>(x, c1w, c1b, bn1g, bn1b, bn1m, bn1v, p_act1);

    // conv2 + fused pool -> act2 (half NHWC pooled), ICB=64 (36 mainloop iterations)
    conv_tc_kernel<256, 128, 24, 8, 2, 4, 2, 261, 136, 2, 0, 64>
        <<<dim3(3, BATCH), 256, SMEM2>>>(p_act1, p_wt2, c2b, bn2g, bn2b, bn2m, bn2v,
                                         p_act2, nullptr);

    // conv3 + fused pool -> out3 (fp32 NCHW) + out3h (half NCHW), ICB=64 (18 iterations)
    conv_tc_kernel<128, 64, 12, 12, 4, 3, 2, 197, 72, 3, 1, 64>
        <<<dim3(1, BATCH), 192, SMEM3>>>(p_act2, p_wt3, c3b, bn3g, bn3b, bn3m, bn3v,
                                         p_out3h, p_out3);

    // FCs (fp16 tensor core)
    gemm_tc_kernel<__half><<<dim3(512 / 32, BATCH / 64), 128>>>(p_out3h, p_fc1wh, fc1b, p_fc1, BATCH, 512, 2304);
    gemm_tc_kernel<__half><<<dim3(256 / 32, BATCH / 64), 128>>>(p_fc1, p_fc2wh, fc2b, p_fc2, BATCH, 256, 512);
    gemm_tc_kernel<float><<<dim3(64 / 32, BATCH / 64), 128>>>(p_fc2, p_attwh, attb, p_q, BATCH, 64, 256);

    // attention + fc3
    attention_kernel<<<BATCH, 64>>>(p_out3, p_q, fc3w, fc3b, outp);
}

// round 15
// speedup vs baseline: 1.6309x; 1.0807x over previous
#include <cuda_runtime.h>
#include <cuda_fp16.h>
#include <math.h>

#define BATCH 512
#define EPS 1e-5f

// ---------------- scratch (no allocations allowed) ----------------
__device__ __half g_act1[BATCH * 24 * 24 * 256];   // NHWC half
__device__ __half g_act2[BATCH * 12 * 12 * 128];   // NHWC half (pooled)
__device__ float  g_out3[BATCH * 64 * 36];         // NCHW fp32 (attention path)
__device__ __half g_out3h[BATCH * 64 * 36];        // NCHW half (fc1 input)
__device__ __half g_fc1[BATCH * 512];
__device__ __half g_fc2[BATCH * 256];
__device__ float  g_q[BATCH * 64];
__device__ __half g_wt2[9 * 256 * 128];            // [tap][ic2][oc][2] pair-interleaved
__device__ __half g_wt3[9 * 128 * 64];
__device__ __half g_fc1wh[512 * 2304];
__device__ __half g_fc2wh[256 * 512];
__device__ __half g_attwh[64 * 256];

__device__ __forceinline__ void cp_async16(void* dst, const void* src) {
    unsigned d = (unsigned)__cvta_generic_to_shared(dst);
    asm volatile("cp.async.ca.shared.global [%0], [%1], 16;" :: "r"(d), "l"(src) : "memory");
}
__device__ __forceinline__ void cp_commit() {
    asm volatile("cp.async.commit_group;" ::: "memory");
}
__device__ __forceinline__ void cp_wait0() {
    asm volatile("cp.async.wait_group 0;" ::: "memory");
}

// ---------------- merged weight conversion kernel ----------------
#define N_WT2 (9 * 256 * 128)
#define N_WT3 (9 * 128 * 64)
#define N_FC1 (512 * 2304)
#define N_FC2 (256 * 512)
#define N_ATT (64 * 256)
__global__ void convert_all_kernel(const float* __restrict__ c2w, const float* __restrict__ c3w,
                                   const float* __restrict__ fc1w, const float* __restrict__ fc2w,
                                   const float* __restrict__ attw,
                                   __half* __restrict__ wt2, __half* __restrict__ wt3,
                                   __half* __restrict__ fc1wh, __half* __restrict__ fc2wh,
                                   __half* __restrict__ attwh) {
    const int total = N_WT2 + N_WT3 + N_FC1 + N_FC2 + N_ATT;
    for (int idx = blockIdx.x * blockDim.x + threadIdx.x; idx < total;
         idx += gridDim.x * blockDim.x) {
        int i = idx;
        if (i < N_WT2) {
            int t = i / (256 * 128);
            int ic = (i / 128) % 256;
            int oc = i % 128;
            float v = c2w[((size_t)oc * 256 + ic) * 9 + t];
            wt2[(((size_t)t * 128 + (ic >> 1)) * 128 + oc) * 2 + (ic & 1)] = __float2half_rn(v);
            continue;
        }
        i -= N_WT2;
        if (i < N_WT3) {
            int t = i / (128 * 64);
            int ic = (i / 64) % 128;
            int oc = i % 64;
            float v = c3w[((size_t)oc * 128 + ic) * 9 + t];
            wt3[(((size_t)t * 64 + (ic >> 1)) * 64 + oc) * 2 + (ic & 1)] = __float2half_rn(v);
            continue;
        }
        i -= N_WT3;
        if (i < N_FC1) { fc1wh[i] = __float2half_rn(fc1w[i]); continue; }
        i -= N_FC1;
        if (i < N_FC2) { fc2wh[i] = __float2half_rn(fc2w[i]); continue; }
        i -= N_FC2;
        attwh[i] = __float2half_rn(attw[i]);
    }
}

// ---------------- block1 (tensor core): conv(1->256,48x48)+BN+ReLU+pool -> NHWC half -----------
#define B1_AP 200
#define B1_WP 136
#define B1_PP 144
__global__ void __launch_bounds__(256, 1)
block1_tc_kernel(const float* __restrict__ x, const float* __restrict__ w,
                 const float* __restrict__ cb, const float* __restrict__ gg,
                 const float* __restrict__ bb, const float* __restrict__ mm,
                 const float* __restrict__ vv, __half* __restrict__ out) {
    extern __shared__ unsigned smem_u[];
    unsigned* aw = smem_u;                       // [8][B1_AP]
    unsigned* ww = aw + 8 * B1_AP;               // [8][B1_WP]
    float* xt = (float*)(ww + 8 * B1_WP);        // [6][50]
    float* sInv = xt + 304;
    float* sBias = sInv + 128;
    __half* pout = (__half*)(sBias + 128);       // [192][B1_PP]

    int strip = blockIdx.x >> 1;
    int nhalf = blockIdx.x & 1;
    int b = blockIdx.y;
    int r0 = strip * 4;
    int oc0 = nhalf * 128;
    int tid = threadIdx.x;
    int warp = tid >> 5, lane = tid & 31;
    int g = lane >> 2, tig = lane & 3;
    int warpM = warp >> 1, warpN = warp & 1;

    const float* xb = x + (size_t)b * 48 * 48;
    for (int i = tid; i < 300; i += 256) {
        int r = i / 50, c = i % 50;
        int gr = r0 - 1 + r, gc = c - 1;
        float v = 0.f;
        if (gr >= 0 && gr < 48 && gc >= 0 && gc < 48) v = xb[gr * 48 + gc];
        xt[r * 50 + c] = v;
    }
    for (int i = tid; i < 8 * 128; i += 256) {
        int k2 = i >> 7, oc = i & 127;
        int t0 = 2 * k2, t1 = 2 * k2 + 1;
        float w0 = (t0 < 9) ? w[(size_t)(oc0 + oc) * 9 + t0] : 0.f;
        float w1 = (t1 < 9) ? w[(size_t)(oc0 + oc) * 9 + t1] : 0.f;
        __half2 h = __floats2half2_rn(w0, w1);
        ww[k2 * B1_WP + oc] = *(unsigned*)&h;
    }
    if (tid < 128) {
        int oc = oc0 + tid;
        float inv = gg[oc] * rsqrtf(vv[oc] + EPS);
        sInv[tid] = inv;
        sBias[tid] = (cb[oc] - mm[oc]) * inv + bb[oc];
    }
    __syncthreads();

    for (int i = tid; i < 8 * 192; i += 256) {
        int k2 = i / 192, m = i % 192;
        int mr = m / 48, mc = m % 48;
        int t0 = 2 * k2, t1 = t0 + 1;
        float v0 = 0.f, v1 = 0.f;
        if (t0 < 9) v0 = xt[(mr + t0 / 3) * 50 + mc + t0 % 3];
        if (t1 < 9) v1 = xt[(mr + t1 / 3) * 50 + mc + t1 % 3];
        __half2 h = __floats2half2_rn(v0, v1);
        aw[k2 * B1_AP + m] = *(unsigned*)&h;
    }
    __syncthreads();

    float acc[3][8][4];
#pragma unroll
    for (int mt = 0; mt < 3; mt++)
#pragma unroll
        for (int nt = 0; nt < 8; nt++)
#pragma unroll
            for (int i = 0; i < 4; i++) acc[mt][nt][i] = 0.f;

#pragma unroll
    for (int mt = 0; mt < 3; mt++) {
        int mbase = warpM * 48 + mt * 16 + g;
        unsigned a0 = aw[tig * B1_AP + mbase];
        unsigned a1 = aw[tig * B1_AP + mbase + 8];
        unsigned a2 = aw[(tig + 4) * B1_AP + mbase];
        unsigned a3 = aw[(tig + 4) * B1_AP + mbase + 8];
#pragma unroll
        for (int nt = 0; nt < 8; nt++) {
            int n = warpN * 64 + nt * 8 + g;
            unsigned b0 = ww[tig * B1_WP + n];
            unsigned b1 = ww[(tig + 4) * B1_WP + n];
            asm volatile(
                "mma.sync.aligned.m16n8k16.row.col.f32.f16.f16.f32 "
                "{%0,%1,%2,%3}, {%4,%5,%6,%7}, {%8,%9}, {%0,%1,%2,%3};"
                : "+f"(acc[mt][nt][0]), "+f"(acc[mt][nt][1]),
                  "+f"(acc[mt][nt][2]), "+f"(acc[mt][nt][3])
                : "r"(a0), "r"(a1), "r"(a2), "r"(a3), "r"(b0), "r"(b1));
        }
    }

#pragma unroll
    for (int mt = 0; mt < 3; mt++) {
        int m = warpM * 48 + mt * 16 + g;
#pragma unroll
        for (int nt = 0; nt < 8; nt++) {
            int oc = warpN * 64 + nt * 8 + tig * 2;
            float inv0 = sInv[oc], bi0 = sBias[oc];
            float inv1 = sInv[oc + 1], bi1 = sBias[oc + 1];
            __half2 v;
            v.x = __float2half_rn(fmaxf(fmaf(acc[mt][nt][0], inv0, bi0), 0.f));
            v.y = __float2half_rn(fmaxf(fmaf(acc[mt][nt][1], inv1, bi1), 0.f));
            *(__half2*)&pout[(size_t)m * B1_PP + oc] = v;
            v.x = __float2half_rn(fmaxf(fmaf(acc[mt][nt][2], inv0, bi0), 0.f));
            v.y = __float2half_rn(fmaxf(fmaf(acc[mt][nt][3], inv1, bi1), 0.f));
            *(__half2*)&pout[(size_t)(m + 8) * B1_PP + oc] = v;
        }
    }
    __syncthreads();

    for (int o = tid; o < 2 * 24 * 128; o += 256) {
        int oc = o & 127;
        int rest = o >> 7;
        int pc = rest % 24, pr = rest / 24;
        int m00 = (2 * pr) * 48 + 2 * pc;
        float a0 = __half2float(pout[(size_t)m00 * B1_PP + oc]);
        float a1 = __half2float(pout[(size_t)(m00 + 1) * B1_PP + oc]);
        float a2 = __half2float(pout[(size_t)(m00 + 48) * B1_PP + oc]);
        float a3 = __half2float(pout[(size_t)(m00 + 49) * B1_PP + oc]);
        float mx = fmaxf(fmaxf(a0, a1), fmaxf(a2, a3));
        int prow = strip * 2 + pr;
        out[(((size_t)b * 24 + prow) * 24 + pc) * 256 + oc0 + oc] = __float2half_rn(mx);
    }
}

// ---------------- fp16 tensor-core implicit-GEMM conv + BN + ReLU + fused 2x2 maxpool ----------
// Position-major A tile (KWP words per position) + ldmatrix.x4 A-fragment loads.
template <int CIN, int COUT, int WIDTH, int SLAB, int RPW, int WM, int WN, int KWP, int WPITCH,
          int OCC, int MODE, int ICB>
__global__ void __launch_bounds__(WM * WN * 32, OCC)
conv_tc_kernel(const __half* __restrict__ act, const __half* __restrict__ wt,
               const float* __restrict__ cb, const float* __restrict__ gg,
               const float* __restrict__ bb, const float* __restrict__ mm,
               const float* __restrict__ vv,
               __half* __restrict__ out_h, float* __restrict__ out_f) {
    constexpr int KW = ICB / 2;
    constexpr int KWQ = KW / 4;
    constexpr int NKS = KW / 8;
    constexpr int HC = WIDTH + 2;
    constexpr int NPOS = (SLAB + 2) * HC;
    constexpr int NT = WM * WN * 32;
    constexpr int NPW = COUT / WN;
    constexpr int NT2 = NPW / 8;
    constexpr int MT = (SLAB * WIDTH) / (WM * 16);
    constexpr int NCH = CIN / ICB;
    constexpr int ITERS = NCH * 9;
    constexpr int QW = KW * COUT / 4;
    constexpr int PFQ = (QW + NT - 1) / NT;
    constexpr int POOLW = WIDTH / 2;
    constexpr int SP = SLAB / 2;

    extern __shared__ float smem[];
    unsigned* atile = (unsigned*)smem;          // [NPOS][KWP] pos-major
    unsigned* wsm = (unsigned*)(smem + NPOS * KWP);   // [2][KW][WPITCH]
    float* sInv = smem + NPOS * KWP + 2 * KW * WPITCH;
    float* sBias = sInv + COUT;
    __half* stage = (__half*)smem;              // reused post-mainloop

    int b = blockIdx.y;
    int r0 = blockIdx.x * SLAB;
    int tid = threadIdx.x;
    int warp = tid >> 5, lane = tid & 31;
    int g = lane >> 2, tig = lane & 3;
    int warpM = warp / WN, warpN = warp % WN;

    if (tid < COUT) {
        float inv = gg[tid] * rsqrtf(vv[tid] + EPS);
        sInv[tid] = inv;
        sBias[tid] = (cb[tid] - mm[tid]) * inv + bb[tid];
    }

    const __half* actb = act + (size_t)b * WIDTH * WIDTH * CIN;

    float acc[MT][NT2][4];
#pragma unroll
    for (int mt = 0; mt < MT; mt++)
#pragma unroll
        for (int nt = 0; nt < NT2; nt++)
#pragma unroll
            for (int i = 0; i < 4; i++) acc[mt][nt][i] = 0.f;

    auto load_atile = [&](int ic0) {
        for (int i = tid; i < NPOS * KWQ; i += NT) {
            int pos = i / KWQ, kq = i % KWQ;
            int tr = pos / HC, tc = pos % HC;
            int ir = r0 - 1 + tr, icl = tc - 1;
            uint4 v = make_uint4(0u, 0u, 0u, 0u);
            if (ir >= 0 && ir < WIDTH && icl >= 0 && icl < WIDTH)
                v = *(const uint4*)&actb[((size_t)ir * WIDTH + icl) * CIN + ic0 + kq * 8];
            *(uint4*)&atile[pos * KWP + kq * 4] = v;   // STS.128, conflict-free
        }
    };
    auto cpw = [&](int it, int buf) {
        const char* base = (const char*)((const unsigned*)wt
            + ((size_t)(it % 9) * (CIN / 2) + (it / 9) * KW) * COUT);
        unsigned* wb = wsm + buf * KW * WPITCH;
#pragma unroll
        for (int q = 0; q < PFQ; q++) {
            int idx = tid + q * NT;
            if (idx < QW) {
                int k2 = idx / (COUT / 4), nq = idx % (COUT / 4);
                cp_async16(&wb[k2 * WPITCH + nq * 4], base + (size_t)idx * 16);
            }
        }
        cp_commit();
    };

    // per-lane ldmatrix base addresses (x4 recipe: lanes 0-15 rows m0-15, lanes 16-31 +16B)
    unsigned atile_u = (unsigned)__cvta_generic_to_shared(atile);
    int mlane = lane & 15;
    int koff = (lane >> 4) * 16;
    unsigned abase[MT];
#pragma unroll
    for (int mt = 0; mt < MT; mt++) {
        int ml = mt * 16 + mlane;
        abase[mt] = atile_u
            + (unsigned)(((warpM * RPW + ml / WIDTH) * HC + ml % WIDTH) * KWP * 4) + koff;
    }

    cpw(0, 0);
    load_atile(0);
    cp_wait0();
    __syncthreads();

    for (int it = 0; it < ITERS; ++it) {
        int buf = it & 1;
        if (it + 1 < ITERS) cpw(it + 1, buf ^ 1);

        int tap = it % 9;
        int dy = tap / 3, dx = tap % 3;
        unsigned tsh = (unsigned)((dy * HC + dx) * KWP * 4);
        const unsigned* wb = wsm + buf * KW * WPITCH;
#pragma unroll
        for (int ks = 0; ks < NKS; ks++) {
            unsigned af[MT][4];
#pragma unroll
            for (int mt = 0; mt < MT; mt++) {
                unsigned addr = abase[mt] + tsh + ks * 32;
                asm volatile(
                    "ldmatrix.sync.aligned.m8n8.x4.shared.b16 {%0,%1,%2,%3}, [%4];"
                    : "=r"(af[mt][0]), "=r"(af[mt][1]), "=r"(af[mt][2]), "=r"(af[mt][3])
                    : "r"(addr));
            }
            int k2c = ks * 8 + tig;
#pragma unroll
            for (int nt = 0; nt < NT2; nt++) {
                int n = warpN * NPW + nt * 8 + g;
                unsigned b0 = wb[k2c * WPITCH + n];
                unsigned b1 = wb[(k2c + 4) * WPITCH + n];
#pragma unroll
                for (int mt = 0; mt < MT; mt++) {
                    asm volatile(
                        "mma.sync.aligned.m16n8k16.row.col.f32.f16.f16.f32 "
                        "{%0,%1,%2,%3}, {%4,%5,%6,%7}, {%8,%9}, {%0,%1,%2,%3};"
                        : "+f"(acc[mt][nt][0]), "+f"(acc[mt][nt][1]),
                          "+f"(acc[mt][nt][2]), "+f"(acc[mt][nt][3])
                        : "r"(af[mt][0]), "r"(af[mt][1]), "r"(af[mt][2]), "r"(af[mt][3]),
                          "r"(b0), "r"(b1));
                }
            }
        }
        if (it + 1 < ITERS) {
            if ((it + 1) % 9 == 0) {
                __syncthreads();
                load_atile(((it + 1) / 9) * ICB);
            }
            cp_wait0();
        }
        __syncthreads();
    }

    // ---- fused epilogue: BN + ReLU -> stage smem, 2x2 maxpool -> global ----
    constexpr int SPITCH = NPW + 8;
    if (MODE == 0) {
        for (int p = 0; p < WN; p++) {
            if (warpN == p) {
#pragma unroll
                for (int mt = 0; mt < MT; mt++) {
                    int m = mt * 16 + g;
                    int pos = (warpM * RPW + m / WIDTH) * WIDTH + m % WIDTH;
                    int m2 = m + 8;
                    int pos2 = (warpM * RPW + m2 / WIDTH) * WIDTH + m2 % WIDTH;
#pragma unroll
                    for (int nt = 0; nt < NT2; nt++) {
                        int ocl = nt * 8 + tig * 2;
                        int oc = p * NPW + ocl;
                        float inv0 = sInv[oc], bi0 = sBias[oc];
                        float inv1 = sInv[oc + 1], bi1 = sBias[oc + 1];
                        __half2 v;
                        v.x = __float2half_rn(fmaxf(fmaf(acc[mt][nt][0], inv0, bi0), 0.f));
                        v.y = __float2half_rn(fmaxf(fmaf(acc[mt][nt][1], inv1, bi1), 0.f));
                        *(__half2*)&stage[(size_t)pos * SPITCH + ocl] = v;
                        v.x = __float2half_rn(fmaxf(fmaf(acc[mt][nt][2], inv0, bi0), 0.f));
                        v.y = __float2half_rn(fmaxf(fmaf(acc[mt][nt][3], inv1, bi1), 0.f));
                        *(__half2*)&stage[(size_t)pos2 * SPITCH + ocl] = v;
                    }
                }
            }
            __syncthreads();
            for (int o = tid; o < SP * POOLW * NPW; o += NT) {
                int ocl = o % NPW;
                int rest = o / NPW;
                int pc = rest % POOLW, pr = rest / POOLW;
                int m00 = (2 * pr) * WIDTH + 2 * pc;
                float a0 = __half2float(stage[(size_t)m00 * SPITCH + ocl]);
                float a1 = __half2float(stage[(size_t)(m00 + 1) * SPITCH + ocl]);
                float a2 = __half2float(stage[(size_t)(m00 + WIDTH) * SPITCH + ocl]);
                float a3 = __half2float(stage[(size_t)(m00 + WIDTH + 1) * SPITCH + ocl]);
                float mx = fmaxf(fmaxf(a0, a1), fmaxf(a2, a3));
                int prow = r0 / 2 + pr;
                out_h[(((size_t)b * POOLW + prow) * POOLW + pc) * COUT + p * NPW + ocl]
                    = __float2half_rn(mx);
            }
            __syncthreads();
        }
    } else {
        constexpr int SP2 = COUT + 8;
#pragma unroll
        for (int mt = 0; mt < MT; mt++) {
            int m = mt * 16 + g;
            int pos = (warpM * RPW + m / WIDTH) * WIDTH + m % WIDTH;
            int m2 = m + 8;
            int pos2 = (warpM * RPW + m2 / WIDTH) * WIDTH + m2 % WIDTH;
#pragma unroll
            for (int nt = 0; nt < NT2; nt++) {
                int oc = warpN * NPW + nt * 8 + tig * 2;
                float inv0 = sInv[oc], bi0 = sBias[oc];
                float inv1 = sInv[oc + 1], bi1 = sBias[oc + 1];
                __half2 v;
                v.x = __float2half_rn(fmaxf(fmaf(acc[mt][nt][0], inv0, bi0), 0.f));
                v.y = __float2half_rn(fmaxf(fmaf(acc[mt][nt][1], inv1, bi1), 0.f));
                *(__half2*)&stage[(size_t)pos * SP2 + oc] = v;
                v.x = __float2half_rn(fmaxf(fmaf(acc[mt][nt][2], inv0, bi0), 0.f));
                v.y = __float2half_rn(fmaxf(fmaf(acc[mt][nt][3], inv1, bi1), 0.f));
                *(__half2*)&stage[(size_t)pos2 * SP2 + oc] = v;
            }
        }
        __syncthreads();
        for (int o = tid; o < SP * POOLW * COUT; o += NT) {
            int oc = o % COUT;
            int rest = o / COUT;
            int pc = rest % POOLW, pr = rest / POOLW;
            int m00 = (2 * pr) * WIDTH + 2 * pc;
            float a0 = __half2float(stage[(size_t)m00 * SP2 + oc]);
            float a1 = __half2float(stage[(size_t)(m00 + 1) * SP2 + oc]);
            float a2 = __half2float(stage[(size_t)(m00 + WIDTH) * SP2 + oc]);
            float a3 = __half2float(stage[(size_t)(m00 + WIDTH + 1) * SP2 + oc]);
            float mx = fmaxf(fmaxf(a0, a1), fmaxf(a2, a3));
            int prow = r0 / 2 + pr;
            size_t oidx = (((size_t)b * COUT + oc) * POOLW + prow) * POOLW + pc;
            out_f[oidx] = mx;
            out_h[oidx] = __float2half_rn(mx);
        }
    }
}

// ---------------- fp16 tensor-core GEMM: C[M,N] = A[M,K] @ W[N,K]^T + bias ----------------
template <typename TOUT>
__global__ void __launch_bounds__(128) gemm_tc_kernel(const __half* __restrict__ A,
                                                      const __half* __restrict__ W,
                                                      const float* __restrict__ bias,
                                                      TOUT* __restrict__ C,
                                                      int M, int N, int K) {
    constexpr int AP = 65, WP = 33;
    __shared__ unsigned As[16 * AP];
    __shared__ unsigned Ws[16 * WP];

    int tid = threadIdx.x;
    int warp = tid >> 5, lane = tid & 31;
    int g = lane >> 2, tig = lane & 3;
    int warpM = warp >> 1, warpN = warp & 1;
    int row0 = blockIdx.y * 64;
    int col0 = blockIdx.x * 32;
    int K2 = K >> 1;
    const unsigned* A_u = (const unsigned*)A;
    const unsigned* W_u = (const unsigned*)W;

    float acc[2][2][4];
#pragma unroll
    for (int mt = 0; mt < 2; mt++)
#pragma unroll
        for (int nt = 0; nt < 2; nt++)
#pragma unroll
            for (int i = 0; i < 4; i++) acc[mt][nt][i] = 0.f;

    uint4 pa[2];
    uint4 pw;

    auto lA = [&](int k0) {
        int k2b = k0 >> 1;
#pragma unroll
        for (int q = 0; q < 2; q++) {
            int idx = tid + q * 128;
            int m = idx >> 2, kq = idx & 3;
            pa[q] = *(const uint4*)&A_u[(size_t)(row0 + m) * K2 + k2b + kq * 4];
        }
        {
            int n = tid >> 2, kq = tid & 3;
            pw = *(const uint4*)&W_u[(size_t)(col0 + n) * K2 + k2b + kq * 4];
        }
    };
    auto sA = [&]() {
#pragma unroll
        for (int q = 0; q < 2; q++) {
            int idx = tid + q * 128;
            int m = idx >> 2, k2 = (idx & 3) * 4;
            As[(k2 + 0) * AP + m] = pa[q].x;
            As[(k2 + 1) * AP + m] = pa[q].y;
            As[(k2 + 2) * AP + m] = pa[q].z;
            As[(k2 + 3) * AP + m] = pa[q].w;
        }
        {
            int n = tid >> 2, k2 = (tid & 3) * 4;
            Ws[(k2 + 0) * WP + n] = pw.x;
            Ws[(k2 + 1) * WP + n] = pw.y;
            Ws[(k2 + 2) * WP + n] = pw.z;
            Ws[(k2 + 3) * WP + n] = pw.w;
        }
    };

    lA(0);
    sA();
    __syncthreads();

    for (int k0 = 0; k0 < K; k0 += 32) {
        if (k0 + 32 < K) lA(k0 + 32);
#pragma unroll
        for (int ks = 0; ks < 2; ks++) {
            int k2c = ks * 8 + tig;
            unsigned af[2][4];
#pragma unroll
            for (int mt = 0; mt < 2; mt++) {
                int m = warpM * 32 + mt * 16 + g;
                af[mt][0] = As[k2c * AP + m];
                af[mt][1] = As[k2c * AP + m + 8];
                af[mt][2] = As[(k2c + 4) * AP + m];
                af[mt][3] = As[(k2c + 4) * AP + m + 8];
            }
#pragma unroll
            for (int nt = 0; nt < 2; nt++) {
                int n = warpN * 16 + nt * 8 + g;
                unsigned b0 = Ws[k2c * WP + n];
                unsigned b1 = Ws[(k2c + 4) * WP + n];
#pragma unroll
                for (int mt = 0; mt < 2; mt++) {
                    asm volatile(
                        "mma.sync.aligned.m16n8k16.row.col.f32.f16.f16.f32 "
                        "{%0,%1,%2,%3}, {%4,%5,%6,%7}, {%8,%9}, {%0,%1,%2,%3};"
                        : "+f"(acc[mt][nt][0]), "+f"(acc[mt][nt][1]),
                          "+f"(acc[mt][nt][2]), "+f"(acc[mt][nt][3])
                        : "r"(af[mt][0]), "r"(af[mt][1]), "r"(af[mt][2]), "r"(af[mt][3]),
                          "r"(b0), "r"(b1));
                }
            }
        }
        __syncthreads();
        if (k0 + 32 < K) {
            sA();
            __syncthreads();
        }
    }

#pragma unroll
    for (int mt = 0; mt < 2; mt++) {
        int r = row0 + warpM * 32 + mt * 16 + g;
#pragma unroll
        for (int nt = 0; nt < 2; nt++) {
            int c = col0 + warpN * 16 + nt * 8 + tig * 2;
            float b0 = bias[c], b1 = bias[c + 1];
            C[(size_t)r * N + c] = (TOUT)(acc[mt][nt][0] + b0);
            C[(size_t)r * N + c + 1] = (TOUT)(acc[mt][nt][1] + b1);
            C[(size_t)(r + 8) * N + c] = (TOUT)(acc[mt][nt][2] + b0);
            C[(size_t)(r + 8) * N + c + 1] = (TOUT)(acc[mt][nt][3] + b1);
        }
    }
}

// ---------------- attention epilogue ----------------
__global__ void attention_kernel(const float* __restrict__ out3, const float* __restrict__ q,
                                 const float* __restrict__ fc3_w, const float* __restrict__ fc3_b,
                                 float* __restrict__ out) {
    int b = blockIdx.x;
    __shared__ float s3[64 * 36];
    __shared__ float sq[64];
    __shared__ float sc[36];
    __shared__ float sg[64];
    int tid = threadIdx.x;
    for (int i = tid; i < 64 * 36; i += 64) s3[i] = out3[(size_t)b * 64 * 36 + i];
    sq[tid] = q[(size_t)b * 64 + tid];
    __syncthreads();
    if (tid < 36) {
        float s = 0.f;
#pragma unroll
        for (int c = 0; c < 64; c++) s = fmaf(s3[c * 36 + tid], sq[c], s);
        sc[tid] = s;
    }
    __syncthreads();
    if (tid == 0) {
        float mx = sc[0];
        for (int i = 1; i < 36; i++) mx = fmaxf(mx, sc[i]);
        float sum = 0.f;
        for (int i = 0; i < 36; i++) { float e = expf(sc[i] - mx); sc[i] = e; sum += e; }
        float invs = 1.f / sum;
        for (int i = 0; i < 36; i++) sc[i] *= invs;
    }
    __syncthreads();
    {
        float s = 0.f;
#pragma unroll
        for (int hw = 0; hw < 36; hw++) s = fmaf(s3[tid * 36 + hw], sc[hw], s);
        sg[tid] = s;
    }
    __syncthreads();
    if (tid < 7) {
        float s = fc3_b[tid];
#pragma unroll
        for (int c = 0; c < 64; c++) s = fmaf(sg[c], fc3_w[tid * 64 + c], s);
        out[(size_t)b * 7 + tid] = s;
    }
}

// ---------------- launch ----------------
extern "C" void kernel_launch(void* const* d_in, const int* in_sizes, int n_in,
                              void* d_out, int out_size) {
    const float* x    = (const float*)d_in[0];
    const float* c1w  = (const float*)d_in[1];
    const float* c1b  = (const float*)d_in[2];
    const float* bn1g = (const float*)d_in[3];
    const float* bn1b = (const float*)d_in[4];
    const float* bn1m = (const float*)d_in[5];
    const float* bn1v = (const float*)d_in[6];
    const float* c2w  = (const float*)d_in[7];
    const float* c2b  = (const float*)d_in[8];
    const float* bn2g = (const float*)d_in[9];
    const float* bn2b = (const float*)d_in[10];
    const float* bn2m = (const float*)d_in[11];
    const float* bn2v = (const float*)d_in[12];
    const float* c3w  = (const float*)d_in[13];
    const float* c3b  = (const float*)d_in[14];
    const float* bn3g = (const float*)d_in[15];
    const float* bn3b = (const float*)d_in[16];
    const float* bn3m = (const float*)d_in[17];
    const float* bn3v = (const float*)d_in[18];
    const float* fc1w = (const float*)d_in[19];
    const float* fc1b = (const float*)d_in[20];
    const float* fc2w = (const float*)d_in[21];
    const float* fc2b = (const float*)d_in[22];
    const float* attw = (const float*)d_in[23];
    const float* attb = (const float*)d_in[24];
    const float* fc3w = (const float*)d_in[25];
    const float* fc3b = (const float*)d_in[26];
    float* outp = (float*)d_out;

    __half *p_act1, *p_act2, *p_out3h, *p_fc1, *p_fc2;
    __half *p_wt2, *p_wt3, *p_fc1wh, *p_fc2wh, *p_attwh;
    float *p_out3, *p_q;
    cudaGetSymbolAddress((void**)&p_act1, g_act1);
    cudaGetSymbolAddress((void**)&p_act2, g_act2);
    cudaGetSymbolAddress((void**)&p_out3, g_out3);
    cudaGetSymbolAddress((void**)&p_out3h, g_out3h);
    cudaGetSymbolAddress((void**)&p_fc1, g_fc1);
    cudaGetSymbolAddress((void**)&p_fc2, g_fc2);
    cudaGetSymbolAddress((void**)&p_q, g_q);
    cudaGetSymbolAddress((void**)&p_wt2, g_wt2);
    cudaGetSymbolAddress((void**)&p_wt3, g_wt3);
    cudaGetSymbolAddress((void**)&p_fc1wh, g_fc1wh);
    cudaGetSymbolAddress((void**)&p_fc2wh, g_fc2wh);
    cudaGetSymbolAddress((void**)&p_attwh, g_attwh);

    // pos-major A tiles, KWP=36 words/pos; ICB=64
    const int SMEM2 = (260 * 36 + 2 * 32 * 136 + 2 * 128) * 4;  // ~73.3 KB, 2 CTAs/SM
    const int SMEM3 = (196 * 36 + 2 * 32 * 72 + 2 * 64) * 4;    // ~47.2 KB, 3 CTAs/SM
    const int SMEMB1 = (8 * B1_AP + 8 * B1_WP + 304 + 256) * 4 + 192 * B1_PP * 2;
    cudaFuncSetAttribute((const void*)conv_tc_kernel<256, 128, 24, 8, 2, 4, 2, 36, 136, 2, 0, 64>,
                         cudaFuncAttributeMaxDynamicSharedMemorySize, SMEM2);
    cudaFuncSetAttribute((const void*)conv_tc_kernel<128, 64, 12, 12, 4, 3, 2, 36, 72, 3, 1, 64>,
                         cudaFuncAttributeMaxDynamicSharedMemorySize, SMEM3);
    cudaFuncSetAttribute((const void*)block1_tc_kernel,
                         cudaFuncAttributeMaxDynamicSharedMemorySize, SMEMB1);

    // merged weight conversions (one launch)
    convert_all_kernel<<<832, 256>>>(c2w, c3w, fc1w, fc2w, attw,
                                     p_wt2, p_wt3, p_fc1wh, p_fc2wh, p_attwh);

    // block1 (tensor core) -> NHWC act1 (half)
    block1_tc_kernel<<<dim3(24, BATCH), 256, SMEMB1>>>(x, c1w, c1b, bn1g, bn1b, bn1m, bn1v, p_act1);

    // conv2 + fused pool -> act2 (half NHWC pooled)
    conv_tc_kernel<256, 128, 24, 8, 2, 4, 2, 36, 136, 2, 0, 64>
        <<<dim3(3, BATCH), 256, SMEM2>>>(p_act1, p_wt2, c2b, bn2g, bn2b, bn2m, bn2v,
                                         p_act2, nullptr);

    // conv3 + fused pool -> out3 (fp32 NCHW) + out3h (half NCHW)
    conv_tc_kernel<128, 64, 12, 12, 4, 3, 2, 36, 72, 3, 1, 64>
        <<<dim3(1, BATCH), 192, SMEM3>>>(p_act2, p_wt3, c3b, bn3g, bn3b, bn3m, bn3v,
                                         p_out3h, p_out3);

    // FCs (fp16 tensor core)
    gemm_tc_kernel<__half><<<dim3(512 / 32, BATCH / 64), 128>>>(p_out3h, p_fc1wh, fc1b, p_fc1, BATCH, 512, 2304);
    gemm_tc_kernel<__half><<<dim3(256 / 32, BATCH / 64), 128>>>(p_fc1, p_fc2wh, fc2b, p_fc2, BATCH, 256, 512);
    gemm_tc_kernel<float><<<dim3(64 / 32, BATCH / 64), 128>>>(p_fc2, p_attwh, attb, p_q, BATCH, 64, 256);

    // attention + fc3
    attention_kernel<<<BATCH, 64>>>(p_out3, p_q, fc3w, fc3b, outp);
}